// round 10
// baseline (speedup 1.0000x reference)
#include <cuda_runtime.h>
#include <cuda_bf16.h>
#include <cub/cub.cuh>
#include <cstdint>

// ---------------- problem constants ----------------
#define BATCH   8
#define NPTS    131072
#define PATCHW  32
#define STRIDEW 16
#define LWIN    8191                    // (131072-32)/16 + 1
#define BL      (BATCH*LWIN)            // 65528
#define BLP     65536                   // padded rows for tile overrun
#define BN      (BATCH*NPTS)            // 1048576
#define TOK     (BL*256)                // tokens elems
#define CEN     (BL*3)                  // centroid elems
#define IDXN    BN                      // sort_idx elems
#define COMBK   192                     // [geo(128) | hp(64)]

// ---------------- static device scratch ----------------
__device__ __align__(256) unsigned long long g_keys[BN];
__device__ __align__(256) unsigned long long g_keys_out[BN];
__device__ __align__(256) unsigned char      g_temp[128u * 1024u * 1024u];
__device__ unsigned                          g_mm[48];
__device__ __align__(16) float               g_sp[BN * 3];
__device__ float                             g_cent[BL * 3];
__device__ __align__(16) __nv_bfloat16       g_comb_hi[(size_t)BLP * COMBK];   // zero-init
__device__ __align__(16) __nv_bfloat16       g_comb_mid[(size_t)BLP * COMBK];  // zero-init
__device__ __align__(16) __nv_bfloat16       g_wb_hi[192 * 256];
__device__ __align__(16) __nv_bfloat16       g_wb_mid[192 * 256];
__device__ __align__(16) float               g_bfold[256];

// ---------------- mma.sync helpers (sm_80+ PTX) ----------------
__device__ __forceinline__ uint32_t smem_u32(const void* p) {
    uint32_t a;
    asm("{ .reg .u64 t; cvta.to.shared.u64 t, %1; cvt.u32.u64 %0, t; }" : "=r"(a) : "l"(p));
    return a;
}
__device__ __forceinline__ void ldsm4(uint32_t* r, uint32_t addr) {
    asm volatile("ldmatrix.sync.aligned.m8n8.x4.shared.b16 {%0,%1,%2,%3}, [%4];"
        : "=r"(r[0]), "=r"(r[1]), "=r"(r[2]), "=r"(r[3]) : "r"(addr));
}
__device__ __forceinline__ void ldsm2t(uint32_t* r, uint32_t addr) {
    asm volatile("ldmatrix.sync.aligned.m8n8.x2.trans.shared.b16 {%0,%1}, [%2];"
        : "=r"(r[0]), "=r"(r[1]) : "r"(addr));
}
__device__ __forceinline__ void mma_bf16(float* d, const uint32_t* a, const uint32_t* b) {
    asm volatile("mma.sync.aligned.m16n8k16.row.col.f32.bf16.bf16.f32 "
        "{%0,%1,%2,%3}, {%4,%5,%6,%7}, {%8,%9}, {%0,%1,%2,%3};"
        : "+f"(d[0]), "+f"(d[1]), "+f"(d[2]), "+f"(d[3])
        : "r"(a[0]), "r"(a[1]), "r"(a[2]), "r"(a[3]), "r"(b[0]), "r"(b[1]));
}
__device__ __forceinline__ void bf16split(float v, __nv_bfloat16& hi, __nv_bfloat16& mid) {
    hi = __float2bfloat16_rn(v);
    mid = __float2bfloat16_rn(v - __bfloat162float(hi));
}

// ---------------- misc helpers ----------------
__device__ __forceinline__ unsigned fenc(float f) {
    unsigned u = __float_as_uint(f);
    return (u & 0x80000000u) ? ~u : (u | 0x80000000u);
}
__device__ __forceinline__ float fdec(unsigned u) {
    return (u & 0x80000000u) ? __uint_as_float(u ^ 0x80000000u) : __uint_as_float(~u);
}
__device__ __forceinline__ unsigned expand10(unsigned v) {
    v &= 0x3FFu;
    v = (v | (v << 16)) & 0x030000FFu;
    v = (v | (v << 8))  & 0x0300F00Fu;
    v = (v | (v << 4))  & 0x030C30C3u;
    v = (v | (v << 2))  & 0x09249249u;
    return v;
}

// ---------------- K: weight fold -> bf16 split (+ g_mm reset in block 192) ----------------
__global__ void __launch_bounds__(256) k_fold(const float* __restrict__ Wproj,
                                              const float* __restrict__ Wp2,
                                              const float* __restrict__ bp2,
                                              const float* __restrict__ bproj) {
    int r = blockIdx.x, c = threadIdx.x;
    if (r < 128) {
        __nv_bfloat16 hi, mid;
        bf16split(Wproj[r * 256 + c], hi, mid);
        g_wb_hi[r * 256 + c] = hi; g_wb_mid[r * 256 + c] = mid;
    } else if (r < 192) {
        int d = r - 128;
        float s = 0.f;
        for (int j = 0; j < 128; j++)
            s = fmaf(Wp2[d * 128 + j], Wproj[(128 + j) * 256 + c], s);
        __nv_bfloat16 hi, mid;
        bf16split(s, hi, mid);
        g_wb_hi[r * 256 + c] = hi; g_wb_mid[r * 256 + c] = mid;
    } else {
        if (c < 48) g_mm[c] = (c & 1) ? 0u : 0xFFFFFFFFu;   // fused k_reset
        float s = bproj[c];
        for (int d = 0; d < 128; d++)
            s = fmaf(bp2[d], Wproj[(128 + d) * 256 + c], s);
        g_bfold[c] = s;
    }
}

// ---------------- K1/K2 ----------------
__global__ void __launch_bounds__(256) k_minmax(const float* __restrict__ pts) {
    int b = blockIdx.x >> 6, chunk = blockIdx.x & 63, t = threadIdx.x;
    unsigned mn0 = ~0u, mn1 = ~0u, mn2 = ~0u, mx0 = 0u, mx1 = 0u, mx2 = 0u;
    size_t base = (size_t)b * NPTS + (size_t)chunk * 2048;
    for (int j = t; j < 2048; j += 256) {
        const float* p = pts + (base + j) * 3;
        unsigned e0 = fenc(p[0]), e1 = fenc(p[1]), e2 = fenc(p[2]);
        mn0 = min(mn0, e0); mx0 = max(mx0, e0);
        mn1 = min(mn1, e1); mx1 = max(mx1, e1);
        mn2 = min(mn2, e2); mx2 = max(mx2, e2);
    }
    mn0 = __reduce_min_sync(0xffffffffu, mn0); mx0 = __reduce_max_sync(0xffffffffu, mx0);
    mn1 = __reduce_min_sync(0xffffffffu, mn1); mx1 = __reduce_max_sync(0xffffffffu, mx1);
    mn2 = __reduce_min_sync(0xffffffffu, mn2); mx2 = __reduce_max_sync(0xffffffffu, mx2);
    __shared__ unsigned s[6];
    if (t < 6) s[t] = (t < 3) ? 0xFFFFFFFFu : 0u;
    __syncthreads();
    if ((t & 31) == 0) {
        atomicMin(&s[0], mn0); atomicMin(&s[1], mn1); atomicMin(&s[2], mn2);
        atomicMax(&s[3], mx0); atomicMax(&s[4], mx1); atomicMax(&s[5], mx2);
    }
    __syncthreads();
    if (t < 3)      atomicMin(&g_mm[b * 6 + t * 2], s[t]);
    else if (t < 6) atomicMax(&g_mm[b * 6 + (t - 3) * 2 + 1], s[t]);
}

__global__ void __launch_bounds__(256) k_keys(const float* __restrict__ pts) {
    int i = blockIdx.x * 256 + threadIdx.x;
    int b = i >> 17;
    int n = i & (NPTS - 1);
    const float* p = pts + (size_t)i * 3;
    unsigned q[3];
#pragma unroll
    for (int a = 0; a < 3; a++) {
        float mn = fdec(g_mm[b * 6 + a * 2]);
        float mx = fdec(g_mm[b * 6 + a * 2 + 1]);
        float sc = fmaxf(__fsub_rn(mx, mn), 1e-8f);
        float r  = __frcp_rn(sc);
        float nr = __fmul_rn(__fsub_rn(p[a], mn), r);
        float tq = __fmul_rn(nr, 1023.0f);
        int qi = (int)tq;
        qi = max(0, min(qi, 1023));
        q[a] = (unsigned)qi;
    }
    unsigned mort = (expand10(q[0]) << 2) | (expand10(q[1]) << 1) | expand10(q[2]);
    g_keys[i] = ((unsigned long long)(unsigned)b << 47) |
                ((unsigned long long)mort << 17) | (unsigned)n;
}

// ---------------- K4: sort_idx + gather ----------------
__global__ void __launch_bounds__(256) k_gather(const float* __restrict__ pts,
                                                float* __restrict__ out, int write_idx) {
    int i = blockIdx.x * 256 + threadIdx.x;
    int b = i >> 17;
    unsigned long long k = g_keys_out[i];
    int idx = (int)(k & 0x1FFFFull);
    if (write_idx) out[TOK + CEN + i] = (float)idx;
    const float* s = pts + (((size_t)b << 17) + (size_t)idx) * 3;
    float* d = g_sp + (size_t)i * 3;
    d[0] = s[0]; d[1] = s[1]; d[2] = s[2];
}

// ---------------- K5: centroids + fused pos-MLP layer 1 ----------------
__global__ void __launch_bounds__(128) k_cent(const float* __restrict__ Wp1,
                                              const float* __restrict__ bp1,
                                              float* __restrict__ out, int write_cent) {
    __shared__ float Wp1s[192], bp1s[64];
    int t = threadIdx.x;
    if (t < 64) {
        Wp1s[t] = Wp1[t]; Wp1s[64 + t] = Wp1[64 + t]; Wp1s[128 + t] = Wp1[128 + t];
        bp1s[t] = bp1[t];
    }
    __syncthreads();
    int m = blockIdx.x * 128 + t;
    if (m >= BL) return;
    int b = m / LWIN, l = m - b * LWIN;
    const float* sp = g_sp + ((size_t)b * NPTS + (size_t)l * STRIDEW) * 3;
    float sx = 0.f, sy = 0.f, sz = 0.f;
#pragma unroll
    for (int p = 0; p < PATCHW; p++) {
        sx += sp[p * 3 + 0]; sy += sp[p * 3 + 1]; sz += sp[p * 3 + 2];
    }
    float cx = sx / 32.0f, cy = sy / 32.0f, cz = sz / 32.0f;
    g_cent[m * 3 + 0] = cx; g_cent[m * 3 + 1] = cy; g_cent[m * 3 + 2] = cz;
    if (write_cent) {
        out[TOK + m * 3 + 0] = cx; out[TOK + m * 3 + 1] = cy; out[TOK + m * 3 + 2] = cz;
    }
    size_t o = (size_t)m * COMBK + 128;
#pragma unroll 8
    for (int ch = 0; ch < 64; ch++) {
        float v = fmaf(cz, Wp1s[128 + ch], fmaf(cy, Wp1s[64 + ch], fmaf(cx, Wp1s[ch], bp1s[ch])));
        v = fmaxf(v, 0.f);
        __nv_bfloat16 hi, mid;
        bf16split(v, hi, mid);
        g_comb_hi[o + ch] = hi; g_comb_mid[o + ch] = mid;
    }
}

// ---------------- K_geo: mma.sync bf16-split GEMM + maxpool ----------------
// Double-buffered h tile (ONE barrier per window); B-fragments loaded per
// window via ldsm2t (no register hoist — R8 post-mortem).
#define GW    16        // windows per block
#define HSTR  72        // bf16 per h row (144B = 9x16B)
#define WSTR  136       // bf16 per W2 row (272B = 17x16B)
// dynamic smem layout (bytes)
#define GS_W2HI  0
#define GS_W2MID (GS_W2HI + 64 * WSTR * 2)       // 17408
#define GS_HHI   (GS_W2MID + 64 * WSTR * 2)      // 34816; two buffers of 32*HSTR*2
#define GS_HMID  (GS_HHI + 2 * 32 * HSTR * 2)    // 44032
#define GS_TOTAL (GS_HMID + 2 * 32 * HSTR * 2)   // 53248

__global__ void __launch_bounds__(128) k_geo(const float* __restrict__ W1,
                                             const float* __restrict__ b1,
                                             const float* __restrict__ W2,
                                             const float* __restrict__ b2) {
    extern __shared__ __align__(16) unsigned char gs[];
    __nv_bfloat16* w2hi_s  = (__nv_bfloat16*)(gs + GS_W2HI);
    __nv_bfloat16* w2mid_s = (__nv_bfloat16*)(gs + GS_W2MID);
    __shared__ float W1s[192], b1s[64], b2s[128];

    int t = threadIdx.x, wi = t >> 5, lane = t & 31;

    if (t < 64) {
        W1s[t] = W1[t]; W1s[64 + t] = W1[64 + t]; W1s[128 + t] = W1[128 + t];
        b1s[t] = b1[t];
    }
    b2s[t] = b2[t];
    for (int i = t; i < 8192; i += 128) {
        int k = i >> 7, c = i & 127;
        float v = W2[i];
        __nv_bfloat16 hi, mid;
        bf16split(v, hi, mid);
        w2hi_s[k * WSTR + c]  = hi;
        w2mid_s[k * WSTR + c] = mid;
    }
    __syncthreads();

    uint32_t w2hi_b = smem_u32(w2hi_s), w2mid_b = smem_u32(w2mid_s);
    uint32_t hhi_b  = smem_u32(gs + GS_HHI), hmid_b = smem_u32(gs + GS_HMID);

    int p  = t & 31;
    int kb = (t >> 5) * 16;

    uint32_t aoff = (uint32_t)(lane & 15) * (HSTR * 2) + (uint32_t)((lane >> 4) & 1) * 16;
    uint32_t boff = (uint32_t)(lane & 15) * (WSTR * 2) + (uint32_t)(wi * 32) * 2;

    for (int w = 0; w < GW; w++) {
        int mi = blockIdx.x * GW + w;
        int m  = min(mi, BL - 1);
        int b  = m / LWIN, l = m - b * LWIN;
        uint32_t hb = (uint32_t)((w & 1) * (32 * HSTR * 2));

        // ---- build h into buffer (w&1); safe: buffer was last read at w-2,
        // and every warp passed the barrier of iteration w-1 after those reads ----
        {
            const float* sp = g_sp + ((size_t)b * NPTS + (size_t)l * STRIDEW + p) * 3;
            float lx = sp[0] - g_cent[m * 3 + 0];
            float ly = sp[1] - g_cent[m * 3 + 1];
            float lz = sp[2] - g_cent[m * 3 + 2];
            __nv_bfloat16* hhi  = (__nv_bfloat16*)(gs + GS_HHI  + hb);
            __nv_bfloat16* hmid = (__nv_bfloat16*)(gs + GS_HMID + hb);
#pragma unroll
            for (int j = 0; j < 16; j += 2) {
                int k = kb + j;
                float v0 = fmaxf(fmaf(lz, W1s[128 + k],
                           fmaf(ly, W1s[64 + k], fmaf(lx, W1s[k], b1s[k]))), 0.f);
                float v1 = fmaxf(fmaf(lz, W1s[128 + k + 1],
                           fmaf(ly, W1s[64 + k + 1], fmaf(lx, W1s[k + 1], b1s[k + 1]))), 0.f);
                uint32_t h2;
                asm("cvt.rn.bf16x2.f32 %0, %1, %2;" : "=r"(h2) : "f"(v1), "f"(v0));
                float h0f = __uint_as_float(h2 << 16);
                float h1f = __uint_as_float(h2 & 0xFFFF0000u);
                uint32_t m2;
                asm("cvt.rn.bf16x2.f32 %0, %1, %2;" : "=r"(m2) : "f"(v1 - h1f), "f"(v0 - h0f));
                *(uint32_t*)&hhi[p * HSTR + k]  = h2;
                *(uint32_t*)&hmid[p * HSTR + k] = m2;
            }
        }
        __syncthreads();   // the ONLY barrier per window

        float acc[2][4][4] = {};
#pragma unroll
        for (int kt = 0; kt < 4; kt++) {
            uint32_t aH[2][4], aM[2][4];
            uint32_t ak = hb + (uint32_t)(kt * 32);
            ldsm4(aH[0], hhi_b  + aoff + ak);
            ldsm4(aH[1], hhi_b  + aoff + ak + 16 * (HSTR * 2));
            ldsm4(aM[0], hmid_b + aoff + ak);
            ldsm4(aM[1], hmid_b + aoff + ak + 16 * (HSTR * 2));
            uint32_t bk = (uint32_t)(kt * 16) * (WSTR * 2);
#pragma unroll
            for (int nt = 0; nt < 4; nt++) {
                uint32_t bH[2], bM[2];
                uint32_t bn = (uint32_t)(nt * 16);
                ldsm2t(bH, w2hi_b  + boff + bk + bn);
                ldsm2t(bM, w2mid_b + boff + bk + bn);
#pragma unroll
                for (int mt = 0; mt < 2; mt++) {
                    mma_bf16(acc[mt][nt], aH[mt], bH);
                    mma_bf16(acc[mt][nt], aH[mt], bM);
                    mma_bf16(acc[mt][nt], aM[mt], bH);
                }
            }
        }

        if (mi < BL) {
#pragma unroll
            for (int nt = 0; nt < 4; nt++) {
                float m0 = fmaxf(fmaxf(acc[0][nt][0], acc[0][nt][2]),
                                 fmaxf(acc[1][nt][0], acc[1][nt][2]));
                float m1 = fmaxf(fmaxf(acc[0][nt][1], acc[0][nt][3]),
                                 fmaxf(acc[1][nt][1], acc[1][nt][3]));
#pragma unroll
                for (int s = 4; s <= 16; s <<= 1) {
                    m0 = fmaxf(m0, __shfl_xor_sync(0xffffffffu, m0, s));
                    m1 = fmaxf(m1, __shfl_xor_sync(0xffffffffu, m1, s));
                }
                if (lane < 4) {
                    int c = wi * 32 + nt * 8 + 2 * lane;
                    float v0 = fmaxf(m0 + b2s[c], 0.f);
                    float v1 = fmaxf(m1 + b2s[c + 1], 0.f);
                    __nv_bfloat16 h0, d0, h1, d1;
                    bf16split(v0, h0, d0);
                    bf16split(v1, h1, d1);
                    size_t o = (size_t)mi * COMBK + c;
                    g_comb_hi[o] = h0;  g_comb_hi[o + 1] = h1;
                    g_comb_mid[o] = d0; g_comb_mid[o + 1] = d1;
                }
            }
        }
    }
}

// ---------------- K7: tokens = comb(BLx192) @ wb(192x256) + bfold ----------------
#define ASTR 200
#define BSTR 72
#define PA_HI  0
#define PA_MID (PA_HI + 64 * ASTR * 2)
#define PB_HI  (PA_MID + 64 * ASTR * 2)
#define PB_MID (PB_HI + 192 * BSTR * 2)
#define P_TOTAL (PB_MID + 192 * BSTR * 2)

__global__ void __launch_bounds__(256) k_proj(float* __restrict__ out) {
    extern __shared__ __align__(16) unsigned char ps[];
    int t = threadIdx.x, wid = t >> 5, lane = t & 31;
    int row0 = blockIdx.x * 64, col0 = blockIdx.y * 64;

#pragma unroll
    for (int j = 0; j < 6; j++) {
        int idx = t + 256 * j;
        int r = idx / 24, kq = (idx % 24) * 8;
        size_t src = (size_t)(row0 + r) * COMBK + kq;
        *(uint4*)(ps + PA_HI  + (r * ASTR + kq) * 2) = *(const uint4*)(g_comb_hi + src);
        *(uint4*)(ps + PA_MID + (r * ASTR + kq) * 2) = *(const uint4*)(g_comb_mid + src);
    }
#pragma unroll
    for (int j = 0; j < 6; j++) {
        int idx = t + 256 * j;
        int k = idx / 8, nq = (idx % 8) * 8;
        size_t src = (size_t)k * 256 + col0 + nq;
        *(uint4*)(ps + PB_HI  + (k * BSTR + nq) * 2) = *(const uint4*)(g_wb_hi + src);
        *(uint4*)(ps + PB_MID + (k * BSTR + nq) * 2) = *(const uint4*)(g_wb_mid + src);
    }
    __syncthreads();

    int wm = wid & 1, wn = wid >> 1;
    uint32_t aHb = smem_u32(ps + PA_HI), aMb = smem_u32(ps + PA_MID);
    uint32_t bHb = smem_u32(ps + PB_HI), bMb = smem_u32(ps + PB_MID);
    uint32_t aoff = (uint32_t)(lane & 15) * (ASTR * 2) + (uint32_t)((lane >> 4) & 1) * 16;
    uint32_t boff = (uint32_t)(lane & 15) * (BSTR * 2) + (uint32_t)(wn * 16) * 2;

    float acc[2][2][4] = {};
#pragma unroll
    for (int kt = 0; kt < 12; kt++) {
        uint32_t aH[2][4], aM[2][4];
#pragma unroll
        for (int mt = 0; mt < 2; mt++) {
            uint32_t ro = (uint32_t)((wm * 32 + mt * 16) * (ASTR * 2)) + kt * 32;
            ldsm4(aH[mt], aHb + aoff + ro);
            ldsm4(aM[mt], aMb + aoff + ro);
        }
        uint32_t bk = (uint32_t)(kt * 16) * (BSTR * 2);
#pragma unroll
        for (int nt = 0; nt < 2; nt++) {
            uint32_t bH[2], bM[2];
            ldsm2t(bH, bHb + boff + bk + nt * 16);
            ldsm2t(bM, bMb + boff + bk + nt * 16);
#pragma unroll
            for (int mt = 0; mt < 2; mt++) {
                mma_bf16(acc[mt][nt], aH[mt], bH);
                mma_bf16(acc[mt][nt], aH[mt], bM);
                mma_bf16(acc[mt][nt], aM[mt], bH);
            }
        }
    }

#pragma unroll
    for (int mt = 0; mt < 2; mt++)
#pragma unroll
        for (int nt = 0; nt < 2; nt++) {
            int r = row0 + wm * 32 + mt * 16 + (lane >> 2);
            int c = col0 + wn * 16 + nt * 8 + (lane & 3) * 2;
            float b0 = g_bfold[c], b1 = g_bfold[c + 1];
            if (r < BL) {
                out[(size_t)r * 256 + c]     = acc[mt][nt][0] + b0;
                out[(size_t)r * 256 + c + 1] = acc[mt][nt][1] + b1;
            }
            if (r + 8 < BL) {
                out[(size_t)(r + 8) * 256 + c]     = acc[mt][nt][2] + b0;
                out[(size_t)(r + 8) * 256 + c + 1] = acc[mt][nt][3] + b1;
            }
        }
}

// ---------------- launch ----------------
extern "C" void kernel_launch(void* const* d_in, const int* in_sizes, int n_in,
                              void* d_out, int out_size) {
    const float* points = (const float*)d_in[0];
    const float* W1   = (const float*)d_in[1];
    const float* b1   = (const float*)d_in[2];
    const float* W2   = (const float*)d_in[3];
    const float* b2   = (const float*)d_in[4];
    const float* Wp1  = (const float*)d_in[5];
    const float* bp1  = (const float*)d_in[6];
    const float* Wp2  = (const float*)d_in[7];
    const float* bp2  = (const float*)d_in[8];
    const float* Wproj = (const float*)d_in[9];
    const float* bproj = (const float*)d_in[10];
    float* out = (float*)d_out;

    int write_cent = (out_size >= TOK + CEN) ? 1 : 0;
    int write_idx  = (out_size >= TOK + CEN + IDXN) ? 1 : 0;

    cudaFuncSetAttribute(k_proj, cudaFuncAttributeMaxDynamicSharedMemorySize, P_TOTAL);
    cudaFuncSetAttribute(k_geo,  cudaFuncAttributeMaxDynamicSharedMemorySize, GS_TOTAL);

    k_fold<<<193, 256>>>(Wproj, Wp2, bp2, bproj);   // includes g_mm reset (block 192)
    k_minmax<<<BATCH * 64, 256>>>(points);
    k_keys<<<BN / 256, 256>>>(points);

    void* d_temp = nullptr;
    unsigned long long* kin = nullptr;
    unsigned long long* kout = nullptr;
    cudaGetSymbolAddress(&d_temp, g_temp);
    cudaGetSymbolAddress((void**)&kin, g_keys);
    cudaGetSymbolAddress((void**)&kout, g_keys_out);

    // bits [0,17) are n and the input is already n-ascending; stable LSD radix
    // over bits [17,50) preserves that tiebreak order => exact stable argsort.
    size_t temp_bytes = 0;
    cub::DeviceRadixSort::SortKeys(nullptr, temp_bytes, kin, kout, BN, 17, 50);
    if (temp_bytes <= sizeof(g_temp)) {
        cub::DeviceRadixSort::SortKeys(d_temp, temp_bytes, kin, kout, BN, 17, 50);
    }

    k_gather<<<BN / 256, 256>>>(points, out, write_idx);
    k_cent<<<(BL + 127) / 128, 128>>>(Wp1, bp1, out, write_cent);
    k_geo<<<(BL + GW - 1) / GW, 128, GS_TOTAL>>>(W1, b1, W2, b2);
    k_proj<<<dim3(BLP / 64, 4), 256, P_TOTAL>>>(out);
}

// round 11
// speedup vs baseline: 1.0496x; 1.0496x over previous
#include <cuda_runtime.h>
#include <cuda_bf16.h>
#include <cub/cub.cuh>
#include <cstdint>

// ---------------- problem constants ----------------
#define BATCH   8
#define NPTS    131072
#define PATCHW  32
#define STRIDEW 16
#define LWIN    8191                    // (131072-32)/16 + 1
#define BL      (BATCH*LWIN)            // 65528
#define BLP     65536                   // padded rows for tile overrun
#define BN      (BATCH*NPTS)            // 1048576
#define TOK     (BL*256)                // tokens elems
#define CEN     (BL*3)                  // centroid elems
#define IDXN    BN                      // sort_idx elems
#define COMBK   192                     // [geo(128) | hp(64)]

// ---------------- static device scratch ----------------
__device__ __align__(256) unsigned long long g_keys[BN];
__device__ __align__(256) unsigned long long g_keys_out[BN];
__device__ __align__(256) unsigned char      g_temp[128u * 1024u * 1024u];
__device__ unsigned                          g_mm[48];
__device__ __align__(16) float               g_sp[BN * 3];
__device__ float                             g_cent[BL * 3];
__device__ __align__(16) __nv_bfloat16       g_comb_hi[(size_t)BLP * COMBK];   // zero-init
__device__ __align__(16) __nv_bfloat16       g_comb_mid[(size_t)BLP * COMBK];  // zero-init
__device__ __align__(16) __nv_bfloat16       g_wb_hi[192 * 256];
__device__ __align__(16) __nv_bfloat16       g_wb_mid[192 * 256];
__device__ __align__(16) float               g_bfold[256];

// ---------------- mma.sync helpers (sm_80+ PTX) ----------------
__device__ __forceinline__ uint32_t smem_u32(const void* p) {
    uint32_t a;
    asm("{ .reg .u64 t; cvta.to.shared.u64 t, %1; cvt.u32.u64 %0, t; }" : "=r"(a) : "l"(p));
    return a;
}
__device__ __forceinline__ void ldsm4(uint32_t* r, uint32_t addr) {
    asm volatile("ldmatrix.sync.aligned.m8n8.x4.shared.b16 {%0,%1,%2,%3}, [%4];"
        : "=r"(r[0]), "=r"(r[1]), "=r"(r[2]), "=r"(r[3]) : "r"(addr));
}
__device__ __forceinline__ void ldsm2t(uint32_t* r, uint32_t addr) {
    asm volatile("ldmatrix.sync.aligned.m8n8.x2.trans.shared.b16 {%0,%1}, [%2];"
        : "=r"(r[0]), "=r"(r[1]) : "r"(addr));
}
__device__ __forceinline__ void mma_bf16(float* d, const uint32_t* a, const uint32_t* b) {
    asm volatile("mma.sync.aligned.m16n8k16.row.col.f32.bf16.bf16.f32 "
        "{%0,%1,%2,%3}, {%4,%5,%6,%7}, {%8,%9}, {%0,%1,%2,%3};"
        : "+f"(d[0]), "+f"(d[1]), "+f"(d[2]), "+f"(d[3])
        : "r"(a[0]), "r"(a[1]), "r"(a[2]), "r"(a[3]), "r"(b[0]), "r"(b[1]));
}
__device__ __forceinline__ void bf16split(float v, __nv_bfloat16& hi, __nv_bfloat16& mid) {
    hi = __float2bfloat16_rn(v);
    mid = __float2bfloat16_rn(v - __bfloat162float(hi));
}

// ---------------- misc helpers ----------------
__device__ __forceinline__ unsigned fenc(float f) {
    unsigned u = __float_as_uint(f);
    return (u & 0x80000000u) ? ~u : (u | 0x80000000u);
}
__device__ __forceinline__ float fdec(unsigned u) {
    return (u & 0x80000000u) ? __uint_as_float(u ^ 0x80000000u) : __uint_as_float(~u);
}
__device__ __forceinline__ unsigned expand10(unsigned v) {
    v &= 0x3FFu;
    v = (v | (v << 16)) & 0x030000FFu;
    v = (v | (v << 8))  & 0x0300F00Fu;
    v = (v | (v << 4))  & 0x030C30C3u;
    v = (v | (v << 2))  & 0x09249249u;
    return v;
}

// ---------------- K: weight fold -> bf16 split (+ g_mm reset in block 192) ----------------
__global__ void __launch_bounds__(256) k_fold(const float* __restrict__ Wproj,
                                              const float* __restrict__ Wp2,
                                              const float* __restrict__ bp2,
                                              const float* __restrict__ bproj) {
    int r = blockIdx.x, c = threadIdx.x;
    if (r < 128) {
        __nv_bfloat16 hi, mid;
        bf16split(Wproj[r * 256 + c], hi, mid);
        g_wb_hi[r * 256 + c] = hi; g_wb_mid[r * 256 + c] = mid;
    } else if (r < 192) {
        int d = r - 128;
        float s = 0.f;
        for (int j = 0; j < 128; j++)
            s = fmaf(Wp2[d * 128 + j], Wproj[(128 + j) * 256 + c], s);
        __nv_bfloat16 hi, mid;
        bf16split(s, hi, mid);
        g_wb_hi[r * 256 + c] = hi; g_wb_mid[r * 256 + c] = mid;
    } else {
        if (c < 48) g_mm[c] = (c & 1) ? 0u : 0xFFFFFFFFu;   // fused k_reset
        float s = bproj[c];
        for (int d = 0; d < 128; d++)
            s = fmaf(bp2[d], Wproj[(128 + d) * 256 + c], s);
        g_bfold[c] = s;
    }
}

// ---------------- K1/K2 ----------------
__global__ void __launch_bounds__(256) k_minmax(const float* __restrict__ pts) {
    int b = blockIdx.x >> 6, chunk = blockIdx.x & 63, t = threadIdx.x;
    unsigned mn0 = ~0u, mn1 = ~0u, mn2 = ~0u, mx0 = 0u, mx1 = 0u, mx2 = 0u;
    size_t base = (size_t)b * NPTS + (size_t)chunk * 2048;
    for (int j = t; j < 2048; j += 256) {
        const float* p = pts + (base + j) * 3;
        unsigned e0 = fenc(p[0]), e1 = fenc(p[1]), e2 = fenc(p[2]);
        mn0 = min(mn0, e0); mx0 = max(mx0, e0);
        mn1 = min(mn1, e1); mx1 = max(mx1, e1);
        mn2 = min(mn2, e2); mx2 = max(mx2, e2);
    }
    mn0 = __reduce_min_sync(0xffffffffu, mn0); mx0 = __reduce_max_sync(0xffffffffu, mx0);
    mn1 = __reduce_min_sync(0xffffffffu, mn1); mx1 = __reduce_max_sync(0xffffffffu, mx1);
    mn2 = __reduce_min_sync(0xffffffffu, mn2); mx2 = __reduce_max_sync(0xffffffffu, mx2);
    __shared__ unsigned s[6];
    if (t < 6) s[t] = (t < 3) ? 0xFFFFFFFFu : 0u;
    __syncthreads();
    if ((t & 31) == 0) {
        atomicMin(&s[0], mn0); atomicMin(&s[1], mn1); atomicMin(&s[2], mn2);
        atomicMax(&s[3], mx0); atomicMax(&s[4], mx1); atomicMax(&s[5], mx2);
    }
    __syncthreads();
    if (t < 3)      atomicMin(&g_mm[b * 6 + t * 2], s[t]);
    else if (t < 6) atomicMax(&g_mm[b * 6 + (t - 3) * 2 + 1], s[t]);
}

__global__ void __launch_bounds__(256) k_keys(const float* __restrict__ pts) {
    int i = blockIdx.x * 256 + threadIdx.x;
    int b = i >> 17;
    int n = i & (NPTS - 1);
    const float* p = pts + (size_t)i * 3;
    unsigned q[3];
#pragma unroll
    for (int a = 0; a < 3; a++) {
        float mn = fdec(g_mm[b * 6 + a * 2]);
        float mx = fdec(g_mm[b * 6 + a * 2 + 1]);
        float sc = fmaxf(__fsub_rn(mx, mn), 1e-8f);
        float r  = __frcp_rn(sc);
        float nr = __fmul_rn(__fsub_rn(p[a], mn), r);
        float tq = __fmul_rn(nr, 1023.0f);
        int qi = (int)tq;
        qi = max(0, min(qi, 1023));
        q[a] = (unsigned)qi;
    }
    unsigned mort = (expand10(q[0]) << 2) | (expand10(q[1]) << 1) | expand10(q[2]);
    g_keys[i] = ((unsigned long long)(unsigned)b << 47) |
                ((unsigned long long)mort << 17) | (unsigned)n;
}

// ---------------- K4: sort_idx + gather ----------------
__global__ void __launch_bounds__(256) k_gather(const float* __restrict__ pts,
                                                float* __restrict__ out, int write_idx) {
    int i = blockIdx.x * 256 + threadIdx.x;
    int b = i >> 17;
    unsigned long long k = g_keys_out[i];
    int idx = (int)(k & 0x1FFFFull);
    if (write_idx) out[TOK + CEN + i] = (float)idx;
    const float* s = pts + (((size_t)b << 17) + (size_t)idx) * 3;
    float* d = g_sp + (size_t)i * 3;
    d[0] = s[0]; d[1] = s[1]; d[2] = s[2];
}

// ---------------- K5: centroids + fused pos-MLP layer 1 ----------------
__global__ void __launch_bounds__(128) k_cent(const float* __restrict__ Wp1,
                                              const float* __restrict__ bp1,
                                              float* __restrict__ out, int write_cent) {
    __shared__ float Wp1s[192], bp1s[64];
    int t = threadIdx.x;
    if (t < 64) {
        Wp1s[t] = Wp1[t]; Wp1s[64 + t] = Wp1[64 + t]; Wp1s[128 + t] = Wp1[128 + t];
        bp1s[t] = bp1[t];
    }
    __syncthreads();
    int m = blockIdx.x * 128 + t;
    if (m >= BL) return;
    int b = m / LWIN, l = m - b * LWIN;
    const float* sp = g_sp + ((size_t)b * NPTS + (size_t)l * STRIDEW) * 3;
    float sx = 0.f, sy = 0.f, sz = 0.f;
#pragma unroll
    for (int p = 0; p < PATCHW; p++) {
        sx += sp[p * 3 + 0]; sy += sp[p * 3 + 1]; sz += sp[p * 3 + 2];
    }
    float cx = sx / 32.0f, cy = sy / 32.0f, cz = sz / 32.0f;
    g_cent[m * 3 + 0] = cx; g_cent[m * 3 + 1] = cy; g_cent[m * 3 + 2] = cz;
    if (write_cent) {
        out[TOK + m * 3 + 0] = cx; out[TOK + m * 3 + 1] = cy; out[TOK + m * 3 + 2] = cz;
    }
    size_t o = (size_t)m * COMBK + 128;
#pragma unroll 8
    for (int ch = 0; ch < 64; ch++) {
        float v = fmaf(cz, Wp1s[128 + ch], fmaf(cy, Wp1s[64 + ch], fmaf(cx, Wp1s[ch], bp1s[ch])));
        v = fmaxf(v, 0.f);
        __nv_bfloat16 hi, mid;
        bf16split(v, hi, mid);
        g_comb_hi[o + ch] = hi; g_comb_mid[o + ch] = mid;
    }
}

// ---------------- K_geo: mma.sync bf16-split GEMM + maxpool (R9 frozen version) ----------------
#define GW    16        // windows per block
#define HSTR  72        // bf16 per h row (144B = 9x16B)
#define WSTR  136       // bf16 per W2 row (272B = 17x16B)

__global__ void __launch_bounds__(128) k_geo(const float* __restrict__ W1,
                                             const float* __restrict__ b1,
                                             const float* __restrict__ W2,
                                             const float* __restrict__ b2) {
    __shared__ __align__(16) __nv_bfloat16 w2hi_s[64 * WSTR];
    __shared__ __align__(16) __nv_bfloat16 w2mid_s[64 * WSTR];
    __shared__ __align__(16) __nv_bfloat16 hhi_s[32 * HSTR];
    __shared__ __align__(16) __nv_bfloat16 hmid_s[32 * HSTR];
    __shared__ float W1s[192], b1s[64], b2s[128];

    int t = threadIdx.x, wi = t >> 5, lane = t & 31;

    if (t < 64) {
        W1s[t] = W1[t]; W1s[64 + t] = W1[64 + t]; W1s[128 + t] = W1[128 + t];
        b1s[t] = b1[t];
    }
    b2s[t] = b2[t];
    for (int i = t; i < 8192; i += 128) {
        int k = i >> 7, c = i & 127;
        float v = W2[i];
        __nv_bfloat16 hi, mid;
        bf16split(v, hi, mid);
        w2hi_s[k * WSTR + c]  = hi;
        w2mid_s[k * WSTR + c] = mid;
    }
    __syncthreads();

    uint32_t hhi_b = smem_u32(hhi_s), hmid_b = smem_u32(hmid_s);
    uint32_t w2hi_b = smem_u32(w2hi_s), w2mid_b = smem_u32(w2mid_s);

    int p  = t & 31;
    int kb = (t >> 5) * 16;

    uint32_t aoff = (uint32_t)(lane & 15) * (HSTR * 2) + (uint32_t)((lane >> 4) & 1) * 16;
    uint32_t boff = (uint32_t)(lane & 15) * (WSTR * 2) + (uint32_t)(wi * 32) * 2;

    for (int w = 0; w < GW; w++) {
        int mi = blockIdx.x * GW + w;
        int m  = min(mi, BL - 1);
        int b  = m / LWIN, l = m - b * LWIN;

        {
            const float* sp = g_sp + ((size_t)b * NPTS + (size_t)l * STRIDEW + p) * 3;
            float lx = sp[0] - g_cent[m * 3 + 0];
            float ly = sp[1] - g_cent[m * 3 + 1];
            float lz = sp[2] - g_cent[m * 3 + 2];
#pragma unroll
            for (int j = 0; j < 16; j += 2) {
                int k = kb + j;
                float v0 = fmaxf(fmaf(lz, W1s[128 + k],
                           fmaf(ly, W1s[64 + k], fmaf(lx, W1s[k], b1s[k]))), 0.f);
                float v1 = fmaxf(fmaf(lz, W1s[128 + k + 1],
                           fmaf(ly, W1s[64 + k + 1], fmaf(lx, W1s[k + 1], b1s[k + 1]))), 0.f);
                uint32_t h2;
                asm("cvt.rn.bf16x2.f32 %0, %1, %2;" : "=r"(h2) : "f"(v1), "f"(v0));
                float h0f = __uint_as_float(h2 << 16);
                float h1f = __uint_as_float(h2 & 0xFFFF0000u);
                uint32_t m2;
                asm("cvt.rn.bf16x2.f32 %0, %1, %2;" : "=r"(m2) : "f"(v1 - h1f), "f"(v0 - h0f));
                *(uint32_t*)&hhi_s[p * HSTR + k]  = h2;
                *(uint32_t*)&hmid_s[p * HSTR + k] = m2;
            }
        }
        __syncthreads();

        float acc[2][4][4] = {};
#pragma unroll
        for (int kt = 0; kt < 4; kt++) {
            uint32_t aH[2][4], aM[2][4];
            uint32_t ak = (uint32_t)(kt * 32);
            ldsm4(aH[0], hhi_b  + aoff + ak);
            ldsm4(aH[1], hhi_b  + aoff + ak + 16 * (HSTR * 2));
            ldsm4(aM[0], hmid_b + aoff + ak);
            ldsm4(aM[1], hmid_b + aoff + ak + 16 * (HSTR * 2));
            uint32_t bk = (uint32_t)(kt * 16) * (WSTR * 2);
#pragma unroll
            for (int nt = 0; nt < 4; nt++) {
                uint32_t bH[2], bM[2];
                uint32_t bn = (uint32_t)(nt * 16);
                ldsm2t(bH, w2hi_b  + boff + bk + bn);
                ldsm2t(bM, w2mid_b + boff + bk + bn);
#pragma unroll
                for (int mt = 0; mt < 2; mt++) {
                    mma_bf16(acc[mt][nt], aH[mt], bH);
                    mma_bf16(acc[mt][nt], aH[mt], bM);
                    mma_bf16(acc[mt][nt], aM[mt], bH);
                }
            }
        }

        if (mi < BL) {
#pragma unroll
            for (int nt = 0; nt < 4; nt++) {
                float m0 = fmaxf(fmaxf(acc[0][nt][0], acc[0][nt][2]),
                                 fmaxf(acc[1][nt][0], acc[1][nt][2]));
                float m1 = fmaxf(fmaxf(acc[0][nt][1], acc[0][nt][3]),
                                 fmaxf(acc[1][nt][1], acc[1][nt][3]));
#pragma unroll
                for (int s = 4; s <= 16; s <<= 1) {
                    m0 = fmaxf(m0, __shfl_xor_sync(0xffffffffu, m0, s));
                    m1 = fmaxf(m1, __shfl_xor_sync(0xffffffffu, m1, s));
                }
                if (lane < 4) {
                    int c = wi * 32 + nt * 8 + 2 * lane;
                    float v0 = fmaxf(m0 + b2s[c], 0.f);
                    float v1 = fmaxf(m1 + b2s[c + 1], 0.f);
                    __nv_bfloat16 h0, d0, h1, d1;
                    bf16split(v0, h0, d0);
                    bf16split(v1, h1, d1);
                    size_t o = (size_t)mi * COMBK + c;
                    g_comb_hi[o] = h0;  g_comb_hi[o + 1] = h1;
                    g_comb_mid[o] = d0; g_comb_mid[o + 1] = d1;
                }
            }
        }
        __syncthreads();
    }
}

// ---------------- K7: tokens = comb(BLx192) @ wb(192x256) + bfold ----------------
// A-tile loaded ONCE per 64-row block; loop over the 4 column tiles reusing it.
#define ASTR 200
#define BSTR 72
#define PA_HI  0
#define PA_MID (PA_HI + 64 * ASTR * 2)
#define PB_HI  (PA_MID + 64 * ASTR * 2)
#define PB_MID (PB_HI + 192 * BSTR * 2)
#define P_TOTAL (PB_MID + 192 * BSTR * 2)

__global__ void __launch_bounds__(256) k_proj(float* __restrict__ out) {
    extern __shared__ __align__(16) unsigned char ps[];
    int t = threadIdx.x, wid = t >> 5, lane = t & 31;
    int row0 = blockIdx.x * 64;

    // load A (64 rows x 192 k), hi & mid — once
#pragma unroll
    for (int j = 0; j < 6; j++) {
        int idx = t + 256 * j;
        int r = idx / 24, kq = (idx % 24) * 8;
        size_t src = (size_t)(row0 + r) * COMBK + kq;
        *(uint4*)(ps + PA_HI  + (r * ASTR + kq) * 2) = *(const uint4*)(g_comb_hi + src);
        *(uint4*)(ps + PA_MID + (r * ASTR + kq) * 2) = *(const uint4*)(g_comb_mid + src);
    }

    int wm = wid & 1, wn = wid >> 1;
    uint32_t aHb = smem_u32(ps + PA_HI), aMb = smem_u32(ps + PA_MID);
    uint32_t bHb = smem_u32(ps + PB_HI), bMb = smem_u32(ps + PB_MID);
    uint32_t aoff = (uint32_t)(lane & 15) * (ASTR * 2) + (uint32_t)((lane >> 4) & 1) * 16;
    uint32_t boff = (uint32_t)(lane & 15) * (BSTR * 2) + (uint32_t)(wn * 16) * 2;

    for (int c4 = 0; c4 < 4; c4++) {
        int col0 = c4 * 64;
        __syncthreads();   // previous iteration's B reads done before overwrite
        // load B (192 k x 64 n), hi & mid
#pragma unroll
        for (int j = 0; j < 6; j++) {
            int idx = t + 256 * j;
            int k = idx / 8, nq = (idx % 8) * 8;
            size_t src = (size_t)k * 256 + col0 + nq;
            *(uint4*)(ps + PB_HI  + (k * BSTR + nq) * 2) = *(const uint4*)(g_wb_hi + src);
            *(uint4*)(ps + PB_MID + (k * BSTR + nq) * 2) = *(const uint4*)(g_wb_mid + src);
        }
        __syncthreads();

        float acc[2][2][4] = {};
#pragma unroll
        for (int kt = 0; kt < 12; kt++) {
            uint32_t aH[2][4], aM[2][4];
#pragma unroll
            for (int mt = 0; mt < 2; mt++) {
                uint32_t ro = (uint32_t)((wm * 32 + mt * 16) * (ASTR * 2)) + kt * 32;
                ldsm4(aH[mt], aHb + aoff + ro);
                ldsm4(aM[mt], aMb + aoff + ro);
            }
            uint32_t bk = (uint32_t)(kt * 16) * (BSTR * 2);
#pragma unroll
            for (int nt = 0; nt < 2; nt++) {
                uint32_t bH[2], bM[2];
                ldsm2t(bH, bHb + boff + bk + nt * 16);
                ldsm2t(bM, bMb + boff + bk + nt * 16);
#pragma unroll
                for (int mt = 0; mt < 2; mt++) {
                    mma_bf16(acc[mt][nt], aH[mt], bH);
                    mma_bf16(acc[mt][nt], aH[mt], bM);
                    mma_bf16(acc[mt][nt], aM[mt], bH);
                }
            }
        }

#pragma unroll
        for (int mt = 0; mt < 2; mt++)
#pragma unroll
            for (int nt = 0; nt < 2; nt++) {
                int r = row0 + wm * 32 + mt * 16 + (lane >> 2);
                int c = col0 + wn * 16 + nt * 8 + (lane & 3) * 2;
                float b0 = g_bfold[c], b1 = g_bfold[c + 1];
                if (r < BL) {
                    out[(size_t)r * 256 + c]     = acc[mt][nt][0] + b0;
                    out[(size_t)r * 256 + c + 1] = acc[mt][nt][1] + b1;
                }
                if (r + 8 < BL) {
                    out[(size_t)(r + 8) * 256 + c]     = acc[mt][nt][2] + b0;
                    out[(size_t)(r + 8) * 256 + c + 1] = acc[mt][nt][3] + b1;
                }
            }
    }
}

// ---------------- launch ----------------
extern "C" void kernel_launch(void* const* d_in, const int* in_sizes, int n_in,
                              void* d_out, int out_size) {
    const float* points = (const float*)d_in[0];
    const float* W1   = (const float*)d_in[1];
    const float* b1   = (const float*)d_in[2];
    const float* W2   = (const float*)d_in[3];
    const float* b2   = (const float*)d_in[4];
    const float* Wp1  = (const float*)d_in[5];
    const float* bp1  = (const float*)d_in[6];
    const float* Wp2  = (const float*)d_in[7];
    const float* bp2  = (const float*)d_in[8];
    const float* Wproj = (const float*)d_in[9];
    const float* bproj = (const float*)d_in[10];
    float* out = (float*)d_out;

    int write_cent = (out_size >= TOK + CEN) ? 1 : 0;
    int write_idx  = (out_size >= TOK + CEN + IDXN) ? 1 : 0;

    cudaFuncSetAttribute(k_proj, cudaFuncAttributeMaxDynamicSharedMemorySize, P_TOTAL);

    k_fold<<<193, 256>>>(Wproj, Wp2, bp2, bproj);   // includes g_mm reset (block 192)
    k_minmax<<<BATCH * 64, 256>>>(points);
    k_keys<<<BN / 256, 256>>>(points);

    void* d_temp = nullptr;
    unsigned long long* kin = nullptr;
    unsigned long long* kout = nullptr;
    cudaGetSymbolAddress(&d_temp, g_temp);
    cudaGetSymbolAddress((void**)&kin, g_keys);
    cudaGetSymbolAddress((void**)&kout, g_keys_out);

    // bits [0,17) are n and the input is already n-ascending; stable LSD radix
    // over bits [17,50) preserves that tiebreak order => exact stable argsort.
    size_t temp_bytes = 0;
    cub::DeviceRadixSort::SortKeys(nullptr, temp_bytes, kin, kout, BN, 17, 50);
    if (temp_bytes <= sizeof(g_temp)) {
        cub::DeviceRadixSort::SortKeys(d_temp, temp_bytes, kin, kout, BN, 17, 50);
    }

    k_gather<<<BN / 256, 256>>>(points, out, write_idx);
    k_cent<<<(BL + 127) / 128, 128>>>(Wp1, bp1, out, write_cent);
    k_geo<<<(BL + GW - 1) / GW, 128>>>(W1, b1, W2, b2);
    k_proj<<<BLP / 64, 256, P_TOTAL>>>(out);
}

// round 12
// speedup vs baseline: 1.1054x; 1.0531x over previous
#include <cuda_runtime.h>
#include <cuda_bf16.h>
#include <cub/cub.cuh>
#include <cstdint>

// ---------------- problem constants ----------------
#define BATCH   8
#define NPTS    131072
#define PATCHW  32
#define STRIDEW 16
#define LWIN    8191                    // (131072-32)/16 + 1
#define BL      (BATCH*LWIN)            // 65528
#define BLP     65536                   // padded rows for tile overrun
#define BN      (BATCH*NPTS)            // 1048576
#define TOK     (BL*256)                // tokens elems
#define CEN     (BL*3)                  // centroid elems
#define IDXN    BN                      // sort_idx elems
#define COMBK   192                     // [geo(128) | hp(64)]

// ---------------- static device scratch ----------------
__device__ __align__(256) unsigned long long g_keys[BN];      // holds 2x uint32[BN]: keys | vals
__device__ __align__(256) unsigned long long g_keys_out[BN];  // holds 2x uint32[BN]
__device__ __align__(256) unsigned char      g_temp[128u * 1024u * 1024u];
__device__ unsigned                          g_mm[48];
__device__ __align__(16) float               g_sp[BN * 3];
__device__ float                             g_cent[BL * 3];
__device__ __align__(16) __nv_bfloat16       g_comb_hi[(size_t)BLP * COMBK];   // zero-init
__device__ __align__(16) __nv_bfloat16       g_comb_mid[(size_t)BLP * COMBK];  // zero-init
__device__ __align__(16) __nv_bfloat16       g_wb_hi[192 * 256];
__device__ __align__(16) __nv_bfloat16       g_wb_mid[192 * 256];
__device__ __align__(16) float               g_bfold[256];

// ---------------- mma.sync helpers (sm_80+ PTX) ----------------
__device__ __forceinline__ uint32_t smem_u32(const void* p) {
    uint32_t a;
    asm("{ .reg .u64 t; cvta.to.shared.u64 t, %1; cvt.u32.u64 %0, t; }" : "=r"(a) : "l"(p));
    return a;
}
__device__ __forceinline__ void ldsm4(uint32_t* r, uint32_t addr) {
    asm volatile("ldmatrix.sync.aligned.m8n8.x4.shared.b16 {%0,%1,%2,%3}, [%4];"
        : "=r"(r[0]), "=r"(r[1]), "=r"(r[2]), "=r"(r[3]) : "r"(addr));
}
__device__ __forceinline__ void ldsm2t(uint32_t* r, uint32_t addr) {
    asm volatile("ldmatrix.sync.aligned.m8n8.x2.trans.shared.b16 {%0,%1}, [%2];"
        : "=r"(r[0]), "=r"(r[1]) : "r"(addr));
}
__device__ __forceinline__ void mma_bf16(float* d, const uint32_t* a, const uint32_t* b) {
    asm volatile("mma.sync.aligned.m16n8k16.row.col.f32.bf16.bf16.f32 "
        "{%0,%1,%2,%3}, {%4,%5,%6,%7}, {%8,%9}, {%0,%1,%2,%3};"
        : "+f"(d[0]), "+f"(d[1]), "+f"(d[2]), "+f"(d[3])
        : "r"(a[0]), "r"(a[1]), "r"(a[2]), "r"(a[3]), "r"(b[0]), "r"(b[1]));
}
__device__ __forceinline__ void bf16split(float v, __nv_bfloat16& hi, __nv_bfloat16& mid) {
    hi = __float2bfloat16_rn(v);
    mid = __float2bfloat16_rn(v - __bfloat162float(hi));
}

// ---------------- misc helpers ----------------
__device__ __forceinline__ unsigned fenc(float f) {
    unsigned u = __float_as_uint(f);
    return (u & 0x80000000u) ? ~u : (u | 0x80000000u);
}
__device__ __forceinline__ float fdec(unsigned u) {
    return (u & 0x80000000u) ? __uint_as_float(u ^ 0x80000000u) : __uint_as_float(~u);
}
__device__ __forceinline__ unsigned expand10(unsigned v) {
    v &= 0x3FFu;
    v = (v | (v << 16)) & 0x030000FFu;
    v = (v | (v << 8))  & 0x0300F00Fu;
    v = (v | (v << 4))  & 0x030C30C3u;
    v = (v | (v << 2))  & 0x09249249u;
    return v;
}

// ---------------- K: weight fold -> bf16 split (+ g_mm reset in block 192) ----------------
__global__ void __launch_bounds__(256) k_fold(const float* __restrict__ Wproj,
                                              const float* __restrict__ Wp2,
                                              const float* __restrict__ bp2,
                                              const float* __restrict__ bproj) {
    int r = blockIdx.x, c = threadIdx.x;
    if (r < 128) {
        __nv_bfloat16 hi, mid;
        bf16split(Wproj[r * 256 + c], hi, mid);
        g_wb_hi[r * 256 + c] = hi; g_wb_mid[r * 256 + c] = mid;
    } else if (r < 192) {
        int d = r - 128;
        float s = 0.f;
        for (int j = 0; j < 128; j++)
            s = fmaf(Wp2[d * 128 + j], Wproj[(128 + j) * 256 + c], s);
        __nv_bfloat16 hi, mid;
        bf16split(s, hi, mid);
        g_wb_hi[r * 256 + c] = hi; g_wb_mid[r * 256 + c] = mid;
    } else {
        if (c < 48) g_mm[c] = (c & 1) ? 0u : 0xFFFFFFFFu;   // fused k_reset
        float s = bproj[c];
        for (int d = 0; d < 128; d++)
            s = fmaf(bp2[d], Wproj[(128 + d) * 256 + c], s);
        g_bfold[c] = s;
    }
}

// ---------------- K1/K2 ----------------
__global__ void __launch_bounds__(256) k_minmax(const float* __restrict__ pts) {
    int b = blockIdx.x >> 6, chunk = blockIdx.x & 63, t = threadIdx.x;
    unsigned mn0 = ~0u, mn1 = ~0u, mn2 = ~0u, mx0 = 0u, mx1 = 0u, mx2 = 0u;
    size_t base = (size_t)b * NPTS + (size_t)chunk * 2048;
    for (int j = t; j < 2048; j += 256) {
        const float* p = pts + (base + j) * 3;
        unsigned e0 = fenc(p[0]), e1 = fenc(p[1]), e2 = fenc(p[2]);
        mn0 = min(mn0, e0); mx0 = max(mx0, e0);
        mn1 = min(mn1, e1); mx1 = max(mx1, e1);
        mn2 = min(mn2, e2); mx2 = max(mx2, e2);
    }
    mn0 = __reduce_min_sync(0xffffffffu, mn0); mx0 = __reduce_max_sync(0xffffffffu, mx0);
    mn1 = __reduce_min_sync(0xffffffffu, mn1); mx1 = __reduce_max_sync(0xffffffffu, mx1);
    mn2 = __reduce_min_sync(0xffffffffu, mn2); mx2 = __reduce_max_sync(0xffffffffu, mx2);
    __shared__ unsigned s[6];
    if (t < 6) s[t] = (t < 3) ? 0xFFFFFFFFu : 0u;
    __syncthreads();
    if ((t & 31) == 0) {
        atomicMin(&s[0], mn0); atomicMin(&s[1], mn1); atomicMin(&s[2], mn2);
        atomicMax(&s[3], mx0); atomicMax(&s[4], mx1); atomicMax(&s[5], mx2);
    }
    __syncthreads();
    if (t < 3)      atomicMin(&g_mm[b * 6 + t * 2], s[t]);
    else if (t < 6) atomicMax(&g_mm[b * 6 + (t - 3) * 2 + 1], s[t]);
}

// 32-bit keys: (b&3)<<30 | morton.  Values: n.  Sorted in two halves (4 batches each).
__global__ void __launch_bounds__(256) k_keys(const float* __restrict__ pts) {
    int i = blockIdx.x * 256 + threadIdx.x;
    int b = i >> 17;
    int n = i & (NPTS - 1);
    const float* p = pts + (size_t)i * 3;
    unsigned q[3];
#pragma unroll
    for (int a = 0; a < 3; a++) {
        float mn = fdec(g_mm[b * 6 + a * 2]);
        float mx = fdec(g_mm[b * 6 + a * 2 + 1]);
        float sc = fmaxf(__fsub_rn(mx, mn), 1e-8f);
        float r  = __frcp_rn(sc);
        float nr = __fmul_rn(__fsub_rn(p[a], mn), r);
        float tq = __fmul_rn(nr, 1023.0f);
        int qi = (int)tq;
        qi = max(0, min(qi, 1023));
        q[a] = (unsigned)qi;
    }
    unsigned mort = (expand10(q[0]) << 2) | (expand10(q[1]) << 1) | expand10(q[2]);
    unsigned* kin = (unsigned*)g_keys;
    unsigned* vin = kin + BN;
    kin[i] = ((unsigned)(b & 3) << 30) | mort;
    vin[i] = (unsigned)n;
}

// ---------------- K4: sort_idx + gather (32-bit values path, proven in R8) ----------------
__global__ void __launch_bounds__(256) k_gather(const float* __restrict__ pts,
                                                float* __restrict__ out, int write_idx) {
    int i = blockIdx.x * 256 + threadIdx.x;
    int b = i >> 17;
    const unsigned* vout = (const unsigned*)g_keys_out + BN;
    int idx = (int)vout[i];
    if (write_idx) out[TOK + CEN + i] = (float)idx;
    const float* s = pts + (((size_t)b << 17) + (size_t)idx) * 3;
    float* d = g_sp + (size_t)i * 3;
    d[0] = s[0]; d[1] = s[1]; d[2] = s[2];
}

// ---------------- K5: centroids + fused pos-MLP layer 1 ----------------
__global__ void __launch_bounds__(128) k_cent(const float* __restrict__ Wp1,
                                              const float* __restrict__ bp1,
                                              float* __restrict__ out, int write_cent) {
    __shared__ float Wp1s[192], bp1s[64];
    int t = threadIdx.x;
    if (t < 64) {
        Wp1s[t] = Wp1[t]; Wp1s[64 + t] = Wp1[64 + t]; Wp1s[128 + t] = Wp1[128 + t];
        bp1s[t] = bp1[t];
    }
    __syncthreads();
    int m = blockIdx.x * 128 + t;
    if (m >= BL) return;
    int b = m / LWIN, l = m - b * LWIN;
    const float* sp = g_sp + ((size_t)b * NPTS + (size_t)l * STRIDEW) * 3;
    float sx = 0.f, sy = 0.f, sz = 0.f;
#pragma unroll
    for (int p = 0; p < PATCHW; p++) {
        sx += sp[p * 3 + 0]; sy += sp[p * 3 + 1]; sz += sp[p * 3 + 2];
    }
    float cx = sx / 32.0f, cy = sy / 32.0f, cz = sz / 32.0f;
    g_cent[m * 3 + 0] = cx; g_cent[m * 3 + 1] = cy; g_cent[m * 3 + 2] = cz;
    if (write_cent) {
        out[TOK + m * 3 + 0] = cx; out[TOK + m * 3 + 1] = cy; out[TOK + m * 3 + 2] = cz;
    }
    size_t o = (size_t)m * COMBK + 128;
#pragma unroll 8
    for (int ch = 0; ch < 64; ch++) {
        float v = fmaf(cz, Wp1s[128 + ch], fmaf(cy, Wp1s[64 + ch], fmaf(cx, Wp1s[ch], bp1s[ch])));
        v = fmaxf(v, 0.f);
        __nv_bfloat16 hi, mid;
        bf16split(v, hi, mid);
        g_comb_hi[o + ch] = hi; g_comb_mid[o + ch] = mid;
    }
}

// ---------------- K_geo: mma.sync bf16-split GEMM + maxpool (R9 frozen version) ----------------
#define GW    16        // windows per block
#define HSTR  72        // bf16 per h row (144B = 9x16B)
#define WSTR  136       // bf16 per W2 row (272B = 17x16B)

__global__ void __launch_bounds__(128) k_geo(const float* __restrict__ W1,
                                             const float* __restrict__ b1,
                                             const float* __restrict__ W2,
                                             const float* __restrict__ b2) {
    __shared__ __align__(16) __nv_bfloat16 w2hi_s[64 * WSTR];
    __shared__ __align__(16) __nv_bfloat16 w2mid_s[64 * WSTR];
    __shared__ __align__(16) __nv_bfloat16 hhi_s[32 * HSTR];
    __shared__ __align__(16) __nv_bfloat16 hmid_s[32 * HSTR];
    __shared__ float W1s[192], b1s[64], b2s[128];

    int t = threadIdx.x, wi = t >> 5, lane = t & 31;

    if (t < 64) {
        W1s[t] = W1[t]; W1s[64 + t] = W1[64 + t]; W1s[128 + t] = W1[128 + t];
        b1s[t] = b1[t];
    }
    b2s[t] = b2[t];
    for (int i = t; i < 8192; i += 128) {
        int k = i >> 7, c = i & 127;
        float v = W2[i];
        __nv_bfloat16 hi, mid;
        bf16split(v, hi, mid);
        w2hi_s[k * WSTR + c]  = hi;
        w2mid_s[k * WSTR + c] = mid;
    }
    __syncthreads();

    uint32_t hhi_b = smem_u32(hhi_s), hmid_b = smem_u32(hmid_s);
    uint32_t w2hi_b = smem_u32(w2hi_s), w2mid_b = smem_u32(w2mid_s);

    int p  = t & 31;
    int kb = (t >> 5) * 16;

    uint32_t aoff = (uint32_t)(lane & 15) * (HSTR * 2) + (uint32_t)((lane >> 4) & 1) * 16;
    uint32_t boff = (uint32_t)(lane & 15) * (WSTR * 2) + (uint32_t)(wi * 32) * 2;

    for (int w = 0; w < GW; w++) {
        int mi = blockIdx.x * GW + w;
        int m  = min(mi, BL - 1);
        int b  = m / LWIN, l = m - b * LWIN;

        {
            const float* sp = g_sp + ((size_t)b * NPTS + (size_t)l * STRIDEW + p) * 3;
            float lx = sp[0] - g_cent[m * 3 + 0];
            float ly = sp[1] - g_cent[m * 3 + 1];
            float lz = sp[2] - g_cent[m * 3 + 2];
#pragma unroll
            for (int j = 0; j < 16; j += 2) {
                int k = kb + j;
                float v0 = fmaxf(fmaf(lz, W1s[128 + k],
                           fmaf(ly, W1s[64 + k], fmaf(lx, W1s[k], b1s[k]))), 0.f);
                float v1 = fmaxf(fmaf(lz, W1s[128 + k + 1],
                           fmaf(ly, W1s[64 + k + 1], fmaf(lx, W1s[k + 1], b1s[k + 1]))), 0.f);
                uint32_t h2;
                asm("cvt.rn.bf16x2.f32 %0, %1, %2;" : "=r"(h2) : "f"(v1), "f"(v0));
                float h0f = __uint_as_float(h2 << 16);
                float h1f = __uint_as_float(h2 & 0xFFFF0000u);
                uint32_t m2;
                asm("cvt.rn.bf16x2.f32 %0, %1, %2;" : "=r"(m2) : "f"(v1 - h1f), "f"(v0 - h0f));
                *(uint32_t*)&hhi_s[p * HSTR + k]  = h2;
                *(uint32_t*)&hmid_s[p * HSTR + k] = m2;
            }
        }
        __syncthreads();

        float acc[2][4][4] = {};
#pragma unroll
        for (int kt = 0; kt < 4; kt++) {
            uint32_t aH[2][4], aM[2][4];
            uint32_t ak = (uint32_t)(kt * 32);
            ldsm4(aH[0], hhi_b  + aoff + ak);
            ldsm4(aH[1], hhi_b  + aoff + ak + 16 * (HSTR * 2));
            ldsm4(aM[0], hmid_b + aoff + ak);
            ldsm4(aM[1], hmid_b + aoff + ak + 16 * (HSTR * 2));
            uint32_t bk = (uint32_t)(kt * 16) * (WSTR * 2);
#pragma unroll
            for (int nt = 0; nt < 4; nt++) {
                uint32_t bH[2], bM[2];
                uint32_t bn = (uint32_t)(nt * 16);
                ldsm2t(bH, w2hi_b  + boff + bk + bn);
                ldsm2t(bM, w2mid_b + boff + bk + bn);
#pragma unroll
                for (int mt = 0; mt < 2; mt++) {
                    mma_bf16(acc[mt][nt], aH[mt], bH);
                    mma_bf16(acc[mt][nt], aH[mt], bM);
                    mma_bf16(acc[mt][nt], aM[mt], bH);
                }
            }
        }

        if (mi < BL) {
#pragma unroll
            for (int nt = 0; nt < 4; nt++) {
                float m0 = fmaxf(fmaxf(acc[0][nt][0], acc[0][nt][2]),
                                 fmaxf(acc[1][nt][0], acc[1][nt][2]));
                float m1 = fmaxf(fmaxf(acc[0][nt][1], acc[0][nt][3]),
                                 fmaxf(acc[1][nt][1], acc[1][nt][3]));
#pragma unroll
                for (int s = 4; s <= 16; s <<= 1) {
                    m0 = fmaxf(m0, __shfl_xor_sync(0xffffffffu, m0, s));
                    m1 = fmaxf(m1, __shfl_xor_sync(0xffffffffu, m1, s));
                }
                if (lane < 4) {
                    int c = wi * 32 + nt * 8 + 2 * lane;
                    float v0 = fmaxf(m0 + b2s[c], 0.f);
                    float v1 = fmaxf(m1 + b2s[c + 1], 0.f);
                    __nv_bfloat16 h0, d0, h1, d1;
                    bf16split(v0, h0, d0);
                    bf16split(v1, h1, d1);
                    size_t o = (size_t)mi * COMBK + c;
                    g_comb_hi[o] = h0;  g_comb_hi[o + 1] = h1;
                    g_comb_mid[o] = d0; g_comb_mid[o + 1] = d1;
                }
            }
        }
        __syncthreads();
    }
}

// ---------------- K7: tokens = comb(BLx192) @ wb(192x256) + bfold ----------------
// A-tile loaded ONCE per 64-row block; loop over the 4 column tiles reusing it.
#define ASTR 200
#define BSTR 72
#define PA_HI  0
#define PA_MID (PA_HI + 64 * ASTR * 2)
#define PB_HI  (PA_MID + 64 * ASTR * 2)
#define PB_MID (PB_HI + 192 * BSTR * 2)
#define P_TOTAL (PB_MID + 192 * BSTR * 2)

__global__ void __launch_bounds__(256) k_proj(float* __restrict__ out) {
    extern __shared__ __align__(16) unsigned char ps[];
    int t = threadIdx.x, wid = t >> 5, lane = t & 31;
    int row0 = blockIdx.x * 64;

#pragma unroll
    for (int j = 0; j < 6; j++) {
        int idx = t + 256 * j;
        int r = idx / 24, kq = (idx % 24) * 8;
        size_t src = (size_t)(row0 + r) * COMBK + kq;
        *(uint4*)(ps + PA_HI  + (r * ASTR + kq) * 2) = *(const uint4*)(g_comb_hi + src);
        *(uint4*)(ps + PA_MID + (r * ASTR + kq) * 2) = *(const uint4*)(g_comb_mid + src);
    }

    int wm = wid & 1, wn = wid >> 1;
    uint32_t aHb = smem_u32(ps + PA_HI), aMb = smem_u32(ps + PA_MID);
    uint32_t bHb = smem_u32(ps + PB_HI), bMb = smem_u32(ps + PB_MID);
    uint32_t aoff = (uint32_t)(lane & 15) * (ASTR * 2) + (uint32_t)((lane >> 4) & 1) * 16;
    uint32_t boff = (uint32_t)(lane & 15) * (BSTR * 2) + (uint32_t)(wn * 16) * 2;

    for (int c4 = 0; c4 < 4; c4++) {
        int col0 = c4 * 64;
        __syncthreads();
#pragma unroll
        for (int j = 0; j < 6; j++) {
            int idx = t + 256 * j;
            int k = idx / 8, nq = (idx % 8) * 8;
            size_t src = (size_t)k * 256 + col0 + nq;
            *(uint4*)(ps + PB_HI  + (k * BSTR + nq) * 2) = *(const uint4*)(g_wb_hi + src);
            *(uint4*)(ps + PB_MID + (k * BSTR + nq) * 2) = *(const uint4*)(g_wb_mid + src);
        }
        __syncthreads();

        float acc[2][2][4] = {};
#pragma unroll
        for (int kt = 0; kt < 12; kt++) {
            uint32_t aH[2][4], aM[2][4];
#pragma unroll
            for (int mt = 0; mt < 2; mt++) {
                uint32_t ro = (uint32_t)((wm * 32 + mt * 16) * (ASTR * 2)) + kt * 32;
                ldsm4(aH[mt], aHb + aoff + ro);
                ldsm4(aM[mt], aMb + aoff + ro);
            }
            uint32_t bk = (uint32_t)(kt * 16) * (BSTR * 2);
#pragma unroll
            for (int nt = 0; nt < 2; nt++) {
                uint32_t bH[2], bM[2];
                ldsm2t(bH, bHb + boff + bk + nt * 16);
                ldsm2t(bM, bMb + boff + bk + nt * 16);
#pragma unroll
                for (int mt = 0; mt < 2; mt++) {
                    mma_bf16(acc[mt][nt], aH[mt], bH);
                    mma_bf16(acc[mt][nt], aH[mt], bM);
                    mma_bf16(acc[mt][nt], aM[mt], bH);
                }
            }
        }

#pragma unroll
        for (int mt = 0; mt < 2; mt++)
#pragma unroll
            for (int nt = 0; nt < 2; nt++) {
                int r = row0 + wm * 32 + mt * 16 + (lane >> 2);
                int c = col0 + wn * 16 + nt * 8 + (lane & 3) * 2;
                float b0 = g_bfold[c], b1 = g_bfold[c + 1];
                if (r < BL) {
                    out[(size_t)r * 256 + c]     = acc[mt][nt][0] + b0;
                    out[(size_t)r * 256 + c + 1] = acc[mt][nt][1] + b1;
                }
                if (r + 8 < BL) {
                    out[(size_t)(r + 8) * 256 + c]     = acc[mt][nt][2] + b0;
                    out[(size_t)(r + 8) * 256 + c + 1] = acc[mt][nt][3] + b1;
                }
            }
    }
}

// ---------------- launch ----------------
extern "C" void kernel_launch(void* const* d_in, const int* in_sizes, int n_in,
                              void* d_out, int out_size) {
    const float* points = (const float*)d_in[0];
    const float* W1   = (const float*)d_in[1];
    const float* b1   = (const float*)d_in[2];
    const float* W2   = (const float*)d_in[3];
    const float* b2   = (const float*)d_in[4];
    const float* Wp1  = (const float*)d_in[5];
    const float* bp1  = (const float*)d_in[6];
    const float* Wp2  = (const float*)d_in[7];
    const float* bp2  = (const float*)d_in[8];
    const float* Wproj = (const float*)d_in[9];
    const float* bproj = (const float*)d_in[10];
    float* out = (float*)d_out;

    int write_cent = (out_size >= TOK + CEN) ? 1 : 0;
    int write_idx  = (out_size >= TOK + CEN + IDXN) ? 1 : 0;

    // one-time side stream + events (created on the first, uncaptured call;
    // reused identically on every call — same captured work each time)
    static cudaStream_t s2 = nullptr;
    static cudaEvent_t ev_fork = nullptr, ev_join = nullptr;
    if (s2 == nullptr) {
        cudaStreamCreateWithFlags(&s2, cudaStreamNonBlocking);
        cudaEventCreateWithFlags(&ev_fork, cudaEventDisableTiming);
        cudaEventCreateWithFlags(&ev_join, cudaEventDisableTiming);
    }

    cudaFuncSetAttribute(k_proj, cudaFuncAttributeMaxDynamicSharedMemorySize, P_TOTAL);

    k_fold<<<193, 256>>>(Wproj, Wp2, bp2, bproj);   // includes g_mm reset (block 192)
    k_minmax<<<BATCH * 64, 256>>>(points);
    k_keys<<<BN / 256, 256>>>(points);

    void* d_temp = nullptr;
    unsigned long long* sym_in = nullptr;
    unsigned long long* sym_out = nullptr;
    cudaGetSymbolAddress(&d_temp, g_temp);
    cudaGetSymbolAddress((void**)&sym_in, g_keys);
    cudaGetSymbolAddress((void**)&sym_out, g_keys_out);
    unsigned* kin  = (unsigned*)sym_in;
    unsigned* vin  = kin + BN;
    unsigned* kout = (unsigned*)sym_out;
    unsigned* vout = kout + BN;
    unsigned char* temp0 = (unsigned char*)d_temp;
    unsigned char* temp1 = temp0 + (64u * 1024u * 1024u);

    // Two stable 4-pass 32-bit sorts (4 batches each), CONCURRENT on two streams.
    // Stability + n-ascending input preserves the exact argsort tiebreak (proven R8).
    size_t temp_bytes = 0;
    cub::DeviceRadixSort::SortPairs(nullptr, temp_bytes, kin, kout, vin, vout,
                                    BN / 2, 0, 32);
    if (temp_bytes <= 64u * 1024u * 1024u) {
        cudaEventRecord(ev_fork, 0);
        cudaStreamWaitEvent(s2, ev_fork, 0);
        size_t tb0 = temp_bytes, tb1 = temp_bytes;
        cub::DeviceRadixSort::SortPairs((void*)temp0, tb0, kin, kout, vin, vout,
                                        BN / 2, 0, 32, (cudaStream_t)0);
        cub::DeviceRadixSort::SortPairs((void*)temp1, tb1, kin + BN / 2, kout + BN / 2,
                                        vin + BN / 2, vout + BN / 2, BN / 2, 0, 32, s2);
        cudaEventRecord(ev_join, s2);
        cudaStreamWaitEvent((cudaStream_t)0, ev_join, 0);
    }

    k_gather<<<BN / 256, 256>>>(points, out, write_idx);
    k_cent<<<(BL + 127) / 128, 128>>>(Wp1, bp1, out, write_cent);
    k_geo<<<(BL + GW - 1) / GW, 128>>>(W1, b1, W2, b2);
    k_proj<<<BLP / 64, 256, P_TOTAL>>>(out);
}

// round 14
// speedup vs baseline: 1.1161x; 1.0097x over previous
#include <cuda_runtime.h>
#include <cuda_bf16.h>
#include <cub/cub.cuh>
#include <cstdint>

// ---------------- problem constants ----------------
#define BATCH   8
#define NPTS    131072
#define PATCHW  32
#define STRIDEW 16
#define LWIN    8191                    // (131072-32)/16 + 1
#define BL      (BATCH*LWIN)            // 65528
#define BLP     65536                   // padded rows for tile overrun
#define BN      (BATCH*NPTS)            // 1048576
#define TOK     (BL*256)                // tokens elems
#define CEN     (BL*3)                  // centroid elems
#define IDXN    BN                      // sort_idx elems
#define COMBK   192                     // [geo(128) | hp(64)]

// ---------------- static device scratch ----------------
__device__ __align__(256) unsigned long long g_keys[BN];      // holds 2x uint32[BN]: keys | vals
__device__ __align__(256) unsigned long long g_keys_out[BN];  // holds 2x uint32[BN]
__device__ __align__(256) unsigned char      g_temp[128u * 1024u * 1024u];
__device__ unsigned                          g_mm[48];
__device__ __align__(16) float               g_sp[BN * 3];
__device__ float                             g_cent[BL * 3];
__device__ __align__(16) __nv_bfloat16       g_comb_hi[(size_t)BLP * COMBK];   // zero-init
__device__ __align__(16) __nv_bfloat16       g_comb_mid[(size_t)BLP * COMBK];  // zero-init
__device__ __align__(16) __nv_bfloat16       g_wb_hi[192 * 256];
__device__ __align__(16) __nv_bfloat16       g_wb_mid[192 * 256];
__device__ __align__(16) float               g_bfold[256];

// ---------------- mma.sync helpers (sm_80+ PTX) ----------------
__device__ __forceinline__ uint32_t smem_u32(const void* p) {
    uint32_t a;
    asm("{ .reg .u64 t; cvta.to.shared.u64 t, %1; cvt.u32.u64 %0, t; }" : "=r"(a) : "l"(p));
    return a;
}
__device__ __forceinline__ void ldsm4(uint32_t* r, uint32_t addr) {
    asm volatile("ldmatrix.sync.aligned.m8n8.x4.shared.b16 {%0,%1,%2,%3}, [%4];"
        : "=r"(r[0]), "=r"(r[1]), "=r"(r[2]), "=r"(r[3]) : "r"(addr));
}
__device__ __forceinline__ void ldsm2t(uint32_t* r, uint32_t addr) {
    asm volatile("ldmatrix.sync.aligned.m8n8.x2.trans.shared.b16 {%0,%1}, [%2];"
        : "=r"(r[0]), "=r"(r[1]) : "r"(addr));
}
__device__ __forceinline__ void mma_bf16(float* d, const uint32_t* a, const uint32_t* b) {
    asm volatile("mma.sync.aligned.m16n8k16.row.col.f32.bf16.bf16.f32 "
        "{%0,%1,%2,%3}, {%4,%5,%6,%7}, {%8,%9}, {%0,%1,%2,%3};"
        : "+f"(d[0]), "+f"(d[1]), "+f"(d[2]), "+f"(d[3])
        : "r"(a[0]), "r"(a[1]), "r"(a[2]), "r"(a[3]), "r"(b[0]), "r"(b[1]));
}
__device__ __forceinline__ void bf16split(float v, __nv_bfloat16& hi, __nv_bfloat16& mid) {
    hi = __float2bfloat16_rn(v);
    mid = __float2bfloat16_rn(v - __bfloat162float(hi));
}

// ---------------- misc helpers ----------------
__device__ __forceinline__ unsigned fenc(float f) {
    unsigned u = __float_as_uint(f);
    return (u & 0x80000000u) ? ~u : (u | 0x80000000u);
}
__device__ __forceinline__ float fdec(unsigned u) {
    return (u & 0x80000000u) ? __uint_as_float(u ^ 0x80000000u) : __uint_as_float(~u);
}
__device__ __forceinline__ unsigned expand10(unsigned v) {
    v &= 0x3FFu;
    v = (v | (v << 16)) & 0x030000FFu;
    v = (v | (v << 8))  & 0x0300F00Fu;
    v = (v | (v << 4))  & 0x030C30C3u;
    v = (v | (v << 2))  & 0x09249249u;
    return v;
}

// ---------------- K: g_mm reset (standalone; fold runs on side stream) ----------------
__global__ void k_reset() {
    int t = threadIdx.x;
    if (t < 48) g_mm[t] = (t & 1) ? 0u : 0xFFFFFFFFu;
}

// ---------------- K: weight fold -> bf16 split (side stream) ----------------
__global__ void __launch_bounds__(256) k_fold(const float* __restrict__ Wproj,
                                              const float* __restrict__ Wp2,
                                              const float* __restrict__ bp2,
                                              const float* __restrict__ bproj) {
    int r = blockIdx.x, c = threadIdx.x;
    if (r < 128) {
        __nv_bfloat16 hi, mid;
        bf16split(Wproj[r * 256 + c], hi, mid);
        g_wb_hi[r * 256 + c] = hi; g_wb_mid[r * 256 + c] = mid;
    } else if (r < 192) {
        int d = r - 128;
        float s = 0.f;
        for (int j = 0; j < 128; j++)
            s = fmaf(Wp2[d * 128 + j], Wproj[(128 + j) * 256 + c], s);
        __nv_bfloat16 hi, mid;
        bf16split(s, hi, mid);
        g_wb_hi[r * 256 + c] = hi; g_wb_mid[r * 256 + c] = mid;
    } else {
        float s = bproj[c];
        for (int d = 0; d < 128; d++)
            s = fmaf(bp2[d], Wproj[(128 + d) * 256 + c], s);
        g_bfold[c] = s;
    }
}

// ---------------- K1/K2 ----------------
__global__ void __launch_bounds__(256) k_minmax(const float* __restrict__ pts) {
    int b = blockIdx.x >> 6, chunk = blockIdx.x & 63, t = threadIdx.x;
    unsigned mn0 = ~0u, mn1 = ~0u, mn2 = ~0u, mx0 = 0u, mx1 = 0u, mx2 = 0u;
    size_t base = (size_t)b * NPTS + (size_t)chunk * 2048;
    for (int j = t; j < 2048; j += 256) {
        const float* p = pts + (base + j) * 3;
        unsigned e0 = fenc(p[0]), e1 = fenc(p[1]), e2 = fenc(p[2]);
        mn0 = min(mn0, e0); mx0 = max(mx0, e0);
        mn1 = min(mn1, e1); mx1 = max(mx1, e1);
        mn2 = min(mn2, e2); mx2 = max(mx2, e2);
    }
    mn0 = __reduce_min_sync(0xffffffffu, mn0); mx0 = __reduce_max_sync(0xffffffffu, mx0);
    mn1 = __reduce_min_sync(0xffffffffu, mn1); mx1 = __reduce_max_sync(0xffffffffu, mx1);
    mn2 = __reduce_min_sync(0xffffffffu, mn2); mx2 = __reduce_max_sync(0xffffffffu, mx2);
    __shared__ unsigned s[6];
    if (t < 6) s[t] = (t < 3) ? 0xFFFFFFFFu : 0u;
    __syncthreads();
    if ((t & 31) == 0) {
        atomicMin(&s[0], mn0); atomicMin(&s[1], mn1); atomicMin(&s[2], mn2);
        atomicMax(&s[3], mx0); atomicMax(&s[4], mx1); atomicMax(&s[5], mx2);
    }
    __syncthreads();
    if (t < 3)      atomicMin(&g_mm[b * 6 + t * 2], s[t]);
    else if (t < 6) atomicMax(&g_mm[b * 6 + (t - 3) * 2 + 1], s[t]);
}

// 32-bit keys: (b&3)<<30 | morton.  Values: n.  Sorted in two halves (4 batches each).
__global__ void __launch_bounds__(256) k_keys(const float* __restrict__ pts) {
    int i = blockIdx.x * 256 + threadIdx.x;
    int b = i >> 17;
    int n = i & (NPTS - 1);
    const float* p = pts + (size_t)i * 3;
    unsigned q[3];
#pragma unroll
    for (int a = 0; a < 3; a++) {
        float mn = fdec(g_mm[b * 6 + a * 2]);
        float mx = fdec(g_mm[b * 6 + a * 2 + 1]);
        float sc = fmaxf(__fsub_rn(mx, mn), 1e-8f);
        float r  = __frcp_rn(sc);
        float nr = __fmul_rn(__fsub_rn(p[a], mn), r);
        float tq = __fmul_rn(nr, 1023.0f);
        int qi = (int)tq;
        qi = max(0, min(qi, 1023));
        q[a] = (unsigned)qi;
    }
    unsigned mort = (expand10(q[0]) << 2) | (expand10(q[1]) << 1) | expand10(q[2]);
    unsigned* kin = (unsigned*)g_keys;
    unsigned* vin = kin + BN;
    kin[i] = ((unsigned)(b & 3) << 30) | mort;
    vin[i] = (unsigned)n;
}

// ---------------- K4: sort_idx + gather (32-bit values path) ----------------
__global__ void __launch_bounds__(256) k_gather(const float* __restrict__ pts,
                                                float* __restrict__ out, int write_idx) {
    int i = blockIdx.x * 256 + threadIdx.x;
    int b = i >> 17;
    const unsigned* vout = (const unsigned*)g_keys_out + BN;
    int idx = (int)vout[i];
    if (write_idx) out[TOK + CEN + i] = (float)idx;
    const float* s = pts + (((size_t)b << 17) + (size_t)idx) * 3;
    float* d = g_sp + (size_t)i * 3;
    d[0] = s[0]; d[1] = s[1]; d[2] = s[2];
}

// ---------------- K5: centroids + fused pos-MLP layer 1 ----------------
__global__ void __launch_bounds__(128) k_cent(const float* __restrict__ Wp1,
                                              const float* __restrict__ bp1,
                                              float* __restrict__ out, int write_cent) {
    __shared__ float Wp1s[192], bp1s[64];
    int t = threadIdx.x;
    if (t < 64) {
        Wp1s[t] = Wp1[t]; Wp1s[64 + t] = Wp1[64 + t]; Wp1s[128 + t] = Wp1[128 + t];
        bp1s[t] = bp1[t];
    }
    __syncthreads();
    int m = blockIdx.x * 128 + t;
    if (m >= BL) return;
    int b = m / LWIN, l = m - b * LWIN;
    const float* sp = g_sp + ((size_t)b * NPTS + (size_t)l * STRIDEW) * 3;
    float sx = 0.f, sy = 0.f, sz = 0.f;
#pragma unroll
    for (int p = 0; p < PATCHW; p++) {
        sx += sp[p * 3 + 0]; sy += sp[p * 3 + 1]; sz += sp[p * 3 + 2];
    }
    float cx = sx / 32.0f, cy = sy / 32.0f, cz = sz / 32.0f;
    g_cent[m * 3 + 0] = cx; g_cent[m * 3 + 1] = cy; g_cent[m * 3 + 2] = cz;
    if (write_cent) {
        out[TOK + m * 3 + 0] = cx; out[TOK + m * 3 + 1] = cy; out[TOK + m * 3 + 2] = cz;
    }
    size_t o = (size_t)m * COMBK + 128;
#pragma unroll 8
    for (int ch = 0; ch < 64; ch++) {
        float v = fmaf(cz, Wp1s[128 + ch], fmaf(cy, Wp1s[64 + ch], fmaf(cx, Wp1s[ch], bp1s[ch])));
        v = fmaxf(v, 0.f);
        __nv_bfloat16 hi, mid;
        bf16split(v, hi, mid);
        g_comb_hi[o + ch] = hi; g_comb_mid[o + ch] = mid;
    }
}

// ---------------- K_geo: mma.sync bf16-split GEMM + maxpool (R9 frozen version) ----------------
#define GW    16        // windows per block
#define HSTR  72        // bf16 per h row (144B = 9x16B)
#define WSTR  136       // bf16 per W2 row (272B = 17x16B)

__global__ void __launch_bounds__(128) k_geo(const float* __restrict__ W1,
                                             const float* __restrict__ b1,
                                             const float* __restrict__ W2,
                                             const float* __restrict__ b2) {
    __shared__ __align__(16) __nv_bfloat16 w2hi_s[64 * WSTR];
    __shared__ __align__(16) __nv_bfloat16 w2mid_s[64 * WSTR];
    __shared__ __align__(16) __nv_bfloat16 hhi_s[32 * HSTR];
    __shared__ __align__(16) __nv_bfloat16 hmid_s[32 * HSTR];
    __shared__ float W1s[192], b1s[64], b2s[128];

    int t = threadIdx.x, wi = t >> 5, lane = t & 31;

    if (t < 64) {
        W1s[t] = W1[t]; W1s[64 + t] = W1[64 + t]; W1s[128 + t] = W1[128 + t];
        b1s[t] = b1[t];
    }
    b2s[t] = b2[t];
    for (int i = t; i < 8192; i += 128) {
        int k = i >> 7, c = i & 127;
        float v = W2[i];
        __nv_bfloat16 hi, mid;
        bf16split(v, hi, mid);
        w2hi_s[k * WSTR + c]  = hi;
        w2mid_s[k * WSTR + c] = mid;
    }
    __syncthreads();

    uint32_t hhi_b = smem_u32(hhi_s), hmid_b = smem_u32(hmid_s);
    uint32_t w2hi_b = smem_u32(w2hi_s), w2mid_b = smem_u32(w2mid_s);

    int p  = t & 31;
    int kb = (t >> 5) * 16;

    uint32_t aoff = (uint32_t)(lane & 15) * (HSTR * 2) + (uint32_t)((lane >> 4) & 1) * 16;
    uint32_t boff = (uint32_t)(lane & 15) * (WSTR * 2) + (uint32_t)(wi * 32) * 2;

    for (int w = 0; w < GW; w++) {
        int mi = blockIdx.x * GW + w;
        int m  = min(mi, BL - 1);
        int b  = m / LWIN, l = m - b * LWIN;

        {
            const float* sp = g_sp + ((size_t)b * NPTS + (size_t)l * STRIDEW + p) * 3;
            float lx = sp[0] - g_cent[m * 3 + 0];
            float ly = sp[1] - g_cent[m * 3 + 1];
            float lz = sp[2] - g_cent[m * 3 + 2];
#pragma unroll
            for (int j = 0; j < 16; j += 2) {
                int k = kb + j;
                float v0 = fmaxf(fmaf(lz, W1s[128 + k],
                           fmaf(ly, W1s[64 + k], fmaf(lx, W1s[k], b1s[k]))), 0.f);
                float v1 = fmaxf(fmaf(lz, W1s[128 + k + 1],
                           fmaf(ly, W1s[64 + k + 1], fmaf(lx, W1s[k + 1], b1s[k + 1]))), 0.f);
                uint32_t h2;
                asm("cvt.rn.bf16x2.f32 %0, %1, %2;" : "=r"(h2) : "f"(v1), "f"(v0));
                float h0f = __uint_as_float(h2 << 16);
                float h1f = __uint_as_float(h2 & 0xFFFF0000u);
                uint32_t m2;
                asm("cvt.rn.bf16x2.f32 %0, %1, %2;" : "=r"(m2) : "f"(v1 - h1f), "f"(v0 - h0f));
                *(uint32_t*)&hhi_s[p * HSTR + k]  = h2;
                *(uint32_t*)&hmid_s[p * HSTR + k] = m2;
            }
        }
        __syncthreads();

        float acc[2][4][4] = {};
#pragma unroll
        for (int kt = 0; kt < 4; kt++) {
            uint32_t aH[2][4], aM[2][4];
            uint32_t ak = (uint32_t)(kt * 32);
            ldsm4(aH[0], hhi_b  + aoff + ak);
            ldsm4(aH[1], hhi_b  + aoff + ak + 16 * (HSTR * 2));
            ldsm4(aM[0], hmid_b + aoff + ak);
            ldsm4(aM[1], hmid_b + aoff + ak + 16 * (HSTR * 2));
            uint32_t bk = (uint32_t)(kt * 16) * (WSTR * 2);
#pragma unroll
            for (int nt = 0; nt < 4; nt++) {
                uint32_t bH[2], bM[2];
                uint32_t bn = (uint32_t)(nt * 16);
                ldsm2t(bH, w2hi_b  + boff + bk + bn);
                ldsm2t(bM, w2mid_b + boff + bk + bn);
#pragma unroll
                for (int mt = 0; mt < 2; mt++) {
                    mma_bf16(acc[mt][nt], aH[mt], bH);
                    mma_bf16(acc[mt][nt], aH[mt], bM);
                    mma_bf16(acc[mt][nt], aM[mt], bH);
                }
            }
        }

        if (mi < BL) {
#pragma unroll
            for (int nt = 0; nt < 4; nt++) {
                float m0 = fmaxf(fmaxf(acc[0][nt][0], acc[0][nt][2]),
                                 fmaxf(acc[1][nt][0], acc[1][nt][2]));
                float m1 = fmaxf(fmaxf(acc[0][nt][1], acc[0][nt][3]),
                                 fmaxf(acc[1][nt][1], acc[1][nt][3]));
#pragma unroll
                for (int s = 4; s <= 16; s <<= 1) {
                    m0 = fmaxf(m0, __shfl_xor_sync(0xffffffffu, m0, s));
                    m1 = fmaxf(m1, __shfl_xor_sync(0xffffffffu, m1, s));
                }
                if (lane < 4) {
                    int c = wi * 32 + nt * 8 + 2 * lane;
                    float v0 = fmaxf(m0 + b2s[c], 0.f);
                    float v1 = fmaxf(m1 + b2s[c + 1], 0.f);
                    __nv_bfloat16 h0, d0, h1, d1;
                    bf16split(v0, h0, d0);
                    bf16split(v1, h1, d1);
                    size_t o = (size_t)mi * COMBK + c;
                    g_comb_hi[o] = h0;  g_comb_hi[o + 1] = h1;
                    g_comb_mid[o] = d0; g_comb_mid[o + 1] = d1;
                }
            }
        }
        __syncthreads();
    }
}

// ---------------- K7: tokens = comb(BLx192) @ wb(192x256) + bfold ----------------
#define ASTR 200
#define BSTR 72
#define PA_HI  0
#define PA_MID (PA_HI + 64 * ASTR * 2)
#define PB_HI  (PA_MID + 64 * ASTR * 2)
#define PB_MID (PB_HI + 192 * BSTR * 2)
#define P_TOTAL (PB_MID + 192 * BSTR * 2)

__global__ void __launch_bounds__(256) k_proj(float* __restrict__ out) {
    extern __shared__ __align__(16) unsigned char ps[];
    int t = threadIdx.x, wid = t >> 5, lane = t & 31;
    int row0 = blockIdx.x * 64;

#pragma unroll
    for (int j = 0; j < 6; j++) {
        int idx = t + 256 * j;
        int r = idx / 24, kq = (idx % 24) * 8;
        size_t src = (size_t)(row0 + r) * COMBK + kq;
        *(uint4*)(ps + PA_HI  + (r * ASTR + kq) * 2) = *(const uint4*)(g_comb_hi + src);
        *(uint4*)(ps + PA_MID + (r * ASTR + kq) * 2) = *(const uint4*)(g_comb_mid + src);
    }

    int wm = wid & 1, wn = wid >> 1;
    uint32_t aHb = smem_u32(ps + PA_HI), aMb = smem_u32(ps + PA_MID);
    uint32_t bHb = smem_u32(ps + PB_HI), bMb = smem_u32(ps + PB_MID);
    uint32_t aoff = (uint32_t)(lane & 15) * (ASTR * 2) + (uint32_t)((lane >> 4) & 1) * 16;
    uint32_t boff = (uint32_t)(lane & 15) * (BSTR * 2) + (uint32_t)(wn * 16) * 2;

    for (int c4 = 0; c4 < 4; c4++) {
        int col0 = c4 * 64;
        __syncthreads();
#pragma unroll
        for (int j = 0; j < 6; j++) {
            int idx = t + 256 * j;
            int k = idx / 8, nq = (idx % 8) * 8;
            size_t src = (size_t)k * 256 + col0 + nq;
            *(uint4*)(ps + PB_HI  + (k * BSTR + nq) * 2) = *(const uint4*)(g_wb_hi + src);
            *(uint4*)(ps + PB_MID + (k * BSTR + nq) * 2) = *(const uint4*)(g_wb_mid + src);
        }
        __syncthreads();

        float acc[2][2][4] = {};
#pragma unroll
        for (int kt = 0; kt < 12; kt++) {
            uint32_t aH[2][4], aM[2][4];
#pragma unroll
            for (int mt = 0; mt < 2; mt++) {
                uint32_t ro = (uint32_t)((wm * 32 + mt * 16) * (ASTR * 2)) + kt * 32;
                ldsm4(aH[mt], aHb + aoff + ro);
                ldsm4(aM[mt], aMb + aoff + ro);
            }
            uint32_t bk = (uint32_t)(kt * 16) * (BSTR * 2);
#pragma unroll
            for (int nt = 0; nt < 2; nt++) {
                uint32_t bH[2], bM[2];
                ldsm2t(bH, bHb + boff + bk + nt * 16);
                ldsm2t(bM, bMb + boff + bk + nt * 16);
#pragma unroll
                for (int mt = 0; mt < 2; mt++) {
                    mma_bf16(acc[mt][nt], aH[mt], bH);
                    mma_bf16(acc[mt][nt], aH[mt], bM);
                    mma_bf16(acc[mt][nt], aM[mt], bH);
                }
            }
        }

#pragma unroll
        for (int mt = 0; mt < 2; mt++)
#pragma unroll
            for (int nt = 0; nt < 2; nt++) {
                int r = row0 + wm * 32 + mt * 16 + (lane >> 2);
                int c = col0 + wn * 16 + nt * 8 + (lane & 3) * 2;
                float b0 = g_bfold[c], b1 = g_bfold[c + 1];
                if (r < BL) {
                    out[(size_t)r * 256 + c]     = acc[mt][nt][0] + b0;
                    out[(size_t)r * 256 + c + 1] = acc[mt][nt][1] + b1;
                }
                if (r + 8 < BL) {
                    out[(size_t)(r + 8) * 256 + c]     = acc[mt][nt][2] + b0;
                    out[(size_t)(r + 8) * 256 + c + 1] = acc[mt][nt][3] + b1;
                }
            }
    }
}

// ---------------- launch ----------------
extern "C" void kernel_launch(void* const* d_in, const int* in_sizes, int n_in,
                              void* d_out, int out_size) {
    const float* points = (const float*)d_in[0];
    const float* W1   = (const float*)d_in[1];
    const float* b1   = (const float*)d_in[2];
    const float* W2   = (const float*)d_in[3];
    const float* b2   = (const float*)d_in[4];
    const float* Wp1  = (const float*)d_in[5];
    const float* bp1  = (const float*)d_in[6];
    const float* Wp2  = (const float*)d_in[7];
    const float* bp2  = (const float*)d_in[8];
    const float* Wproj = (const float*)d_in[9];
    const float* bproj = (const float*)d_in[10];
    float* out = (float*)d_out;

    int write_cent = (out_size >= TOK + CEN) ? 1 : 0;
    int write_idx  = (out_size >= TOK + CEN + IDXN) ? 1 : 0;

    // one side stream + 3 events, created once (same footprint class as the
    // passing R12 run: 1 stream; R13's 8-stream version tripped the mem guard)
    static cudaStream_t s2 = nullptr;
    static cudaEvent_t ev_begin = nullptr, ev_fork = nullptr, ev_join = nullptr;
    if (s2 == nullptr) {
        cudaStreamCreateWithFlags(&s2, cudaStreamNonBlocking);
        cudaEventCreateWithFlags(&ev_begin, cudaEventDisableTiming);
        cudaEventCreateWithFlags(&ev_fork, cudaEventDisableTiming);
        cudaEventCreateWithFlags(&ev_join, cudaEventDisableTiming);
    }

    cudaFuncSetAttribute(k_proj, cudaFuncAttributeMaxDynamicSharedMemorySize, P_TOTAL);

    // fold on the side stream, overlapping minmax/keys/sort-half-0
    cudaEventRecord(ev_begin, 0);
    cudaStreamWaitEvent(s2, ev_begin, 0);
    k_fold<<<193, 256, 0, s2>>>(Wproj, Wp2, bp2, bproj);

    k_reset<<<1, 64>>>();
    k_minmax<<<BATCH * 64, 256>>>(points);
    k_keys<<<BN / 256, 256>>>(points);

    void* d_temp = nullptr;
    unsigned long long* sym_in = nullptr;
    unsigned long long* sym_out = nullptr;
    cudaGetSymbolAddress(&d_temp, g_temp);
    cudaGetSymbolAddress((void**)&sym_in, g_keys);
    cudaGetSymbolAddress((void**)&sym_out, g_keys_out);
    unsigned* kin  = (unsigned*)sym_in;
    unsigned* vin  = kin + BN;
    unsigned* kout = (unsigned*)sym_out;
    unsigned* vout = kout + BN;
    unsigned char* temp0 = (unsigned char*)d_temp;
    unsigned char* temp1 = temp0 + (64u * 1024u * 1024u);

    // Two stable 4-pass 32-bit sorts (4 batches each), CONCURRENT on two streams.
    // Stability + n-ascending input preserves the exact argsort tiebreak.
    size_t temp_bytes = 0;
    cub::DeviceRadixSort::SortPairs(nullptr, temp_bytes, kin, kout, vin, vout,
                                    BN / 2, 0, 32);
    if (temp_bytes <= 64u * 1024u * 1024u) {
        cudaEventRecord(ev_fork, 0);
        cudaStreamWaitEvent(s2, ev_fork, 0);     // s2: after fold, wait for keys
        size_t tb0 = temp_bytes, tb1 = temp_bytes;
        cub::DeviceRadixSort::SortPairs((void*)temp0, tb0, kin, kout, vin, vout,
                                        BN / 2, 0, 32, (cudaStream_t)0);
        cub::DeviceRadixSort::SortPairs((void*)temp1, tb1, kin + BN / 2, kout + BN / 2,
                                        vin + BN / 2, vout + BN / 2, BN / 2, 0, 32, s2);
        cudaEventRecord(ev_join, s2);            // orders fold AND sort-half-1
        cudaStreamWaitEvent((cudaStream_t)0, ev_join, 0);
    }

    k_gather<<<BN / 256, 256>>>(points, out, write_idx);
    k_cent<<<(BL + 127) / 128, 128>>>(Wp1, bp1, out, write_cent);
    k_geo<<<(BL + GW - 1) / GW, 128>>>(W1, b1, W2, b2);
    k_proj<<<BLP / 64, 256, P_TOTAL>>>(out);
}

// round 15
// speedup vs baseline: 1.1223x; 1.0056x over previous
#include <cuda_runtime.h>
#include <cuda_bf16.h>
#include <cub/cub.cuh>
#include <cstdint>

// ---------------- problem constants ----------------
#define BATCH   8
#define NPTS    131072
#define PATCHW  32
#define STRIDEW 16
#define LWIN    8191                    // (131072-32)/16 + 1
#define BL      (BATCH*LWIN)            // 65528
#define BLP     65536                   // padded rows for tile overrun
#define BN      (BATCH*NPTS)            // 1048576
#define TOK     (BL*256)                // tokens elems
#define CEN     (BL*3)                  // centroid elems
#define IDXN    BN                      // sort_idx elems
#define COMBK   192                     // [geo(128) | hp(64)]
#define HALFW   (4*LWIN)                // windows in half (32764)

// ---------------- static device scratch ----------------
__device__ __align__(256) unsigned long long g_keys[BN];      // holds 2x uint32[BN]: keys | vals
__device__ __align__(256) unsigned long long g_keys_out[BN];  // holds 2x uint32[BN]
__device__ __align__(256) unsigned char      g_temp[128u * 1024u * 1024u];
__device__ unsigned                          g_mm[48];
__device__ __align__(16) float               g_sp[BN * 3];
__device__ float                             g_cent[BL * 3];
__device__ __align__(16) __nv_bfloat16       g_comb_hi[(size_t)BLP * COMBK];   // zero-init
__device__ __align__(16) __nv_bfloat16       g_comb_mid[(size_t)BLP * COMBK];  // zero-init
__device__ __align__(16) __nv_bfloat16       g_wb_hi[192 * 256];
__device__ __align__(16) __nv_bfloat16       g_wb_mid[192 * 256];
__device__ __align__(16) float               g_bfold[256];

// ---------------- mma.sync helpers (sm_80+ PTX) ----------------
__device__ __forceinline__ uint32_t smem_u32(const void* p) {
    uint32_t a;
    asm("{ .reg .u64 t; cvta.to.shared.u64 t, %1; cvt.u32.u64 %0, t; }" : "=r"(a) : "l"(p));
    return a;
}
__device__ __forceinline__ void ldsm4(uint32_t* r, uint32_t addr) {
    asm volatile("ldmatrix.sync.aligned.m8n8.x4.shared.b16 {%0,%1,%2,%3}, [%4];"
        : "=r"(r[0]), "=r"(r[1]), "=r"(r[2]), "=r"(r[3]) : "r"(addr));
}
__device__ __forceinline__ void ldsm2t(uint32_t* r, uint32_t addr) {
    asm volatile("ldmatrix.sync.aligned.m8n8.x2.trans.shared.b16 {%0,%1}, [%2];"
        : "=r"(r[0]), "=r"(r[1]) : "r"(addr));
}
__device__ __forceinline__ void mma_bf16(float* d, const uint32_t* a, const uint32_t* b) {
    asm volatile("mma.sync.aligned.m16n8k16.row.col.f32.bf16.bf16.f32 "
        "{%0,%1,%2,%3}, {%4,%5,%6,%7}, {%8,%9}, {%0,%1,%2,%3};"
        : "+f"(d[0]), "+f"(d[1]), "+f"(d[2]), "+f"(d[3])
        : "r"(a[0]), "r"(a[1]), "r"(a[2]), "r"(a[3]), "r"(b[0]), "r"(b[1]));
}
__device__ __forceinline__ void bf16split(float v, __nv_bfloat16& hi, __nv_bfloat16& mid) {
    hi = __float2bfloat16_rn(v);
    mid = __float2bfloat16_rn(v - __bfloat162float(hi));
}

// ---------------- misc helpers ----------------
__device__ __forceinline__ unsigned fenc(float f) {
    unsigned u = __float_as_uint(f);
    return (u & 0x80000000u) ? ~u : (u | 0x80000000u);
}
__device__ __forceinline__ float fdec(unsigned u) {
    return (u & 0x80000000u) ? __uint_as_float(u ^ 0x80000000u) : __uint_as_float(~u);
}
__device__ __forceinline__ unsigned expand10(unsigned v) {
    v &= 0x3FFu;
    v = (v | (v << 16)) & 0x030000FFu;
    v = (v | (v << 8))  & 0x0300F00Fu;
    v = (v | (v << 4))  & 0x030C30C3u;
    v = (v | (v << 2))  & 0x09249249u;
    return v;
}

// ---------------- K: g_mm reset ----------------
__global__ void k_reset() {
    int t = threadIdx.x;
    if (t < 48) g_mm[t] = (t & 1) ? 0u : 0xFFFFFFFFu;
}

// ---------------- K: weight fold -> bf16 split (side stream) ----------------
__global__ void __launch_bounds__(256) k_fold(const float* __restrict__ Wproj,
                                              const float* __restrict__ Wp2,
                                              const float* __restrict__ bp2,
                                              const float* __restrict__ bproj) {
    int r = blockIdx.x, c = threadIdx.x;
    if (r < 128) {
        __nv_bfloat16 hi, mid;
        bf16split(Wproj[r * 256 + c], hi, mid);
        g_wb_hi[r * 256 + c] = hi; g_wb_mid[r * 256 + c] = mid;
    } else if (r < 192) {
        int d = r - 128;
        float s = 0.f;
        for (int j = 0; j < 128; j++)
            s = fmaf(Wp2[d * 128 + j], Wproj[(128 + j) * 256 + c], s);
        __nv_bfloat16 hi, mid;
        bf16split(s, hi, mid);
        g_wb_hi[r * 256 + c] = hi; g_wb_mid[r * 256 + c] = mid;
    } else {
        float s = bproj[c];
        for (int d = 0; d < 128; d++)
            s = fmaf(bp2[d], Wproj[(128 + d) * 256 + c], s);
        g_bfold[c] = s;
    }
}

// ---------------- K1/K2 ----------------
__global__ void __launch_bounds__(256) k_minmax(const float* __restrict__ pts) {
    int b = blockIdx.x >> 6, chunk = blockIdx.x & 63, t = threadIdx.x;
    unsigned mn0 = ~0u, mn1 = ~0u, mn2 = ~0u, mx0 = 0u, mx1 = 0u, mx2 = 0u;
    size_t base = (size_t)b * NPTS + (size_t)chunk * 2048;
    for (int j = t; j < 2048; j += 256) {
        const float* p = pts + (base + j) * 3;
        unsigned e0 = fenc(p[0]), e1 = fenc(p[1]), e2 = fenc(p[2]);
        mn0 = min(mn0, e0); mx0 = max(mx0, e0);
        mn1 = min(mn1, e1); mx1 = max(mx1, e1);
        mn2 = min(mn2, e2); mx2 = max(mx2, e2);
    }
    mn0 = __reduce_min_sync(0xffffffffu, mn0); mx0 = __reduce_max_sync(0xffffffffu, mx0);
    mn1 = __reduce_min_sync(0xffffffffu, mn1); mx1 = __reduce_max_sync(0xffffffffu, mx1);
    mn2 = __reduce_min_sync(0xffffffffu, mn2); mx2 = __reduce_max_sync(0xffffffffu, mx2);
    __shared__ unsigned s[6];
    if (t < 6) s[t] = (t < 3) ? 0xFFFFFFFFu : 0u;
    __syncthreads();
    if ((t & 31) == 0) {
        atomicMin(&s[0], mn0); atomicMin(&s[1], mn1); atomicMin(&s[2], mn2);
        atomicMax(&s[3], mx0); atomicMax(&s[4], mx1); atomicMax(&s[5], mx2);
    }
    __syncthreads();
    if (t < 3)      atomicMin(&g_mm[b * 6 + t * 2], s[t]);
    else if (t < 6) atomicMax(&g_mm[b * 6 + (t - 3) * 2 + 1], s[t]);
}

// 32-bit keys: (b&3)<<30 | morton.  Values: n.  Sorted in two halves (4 batches each).
__global__ void __launch_bounds__(256) k_keys(const float* __restrict__ pts) {
    int i = blockIdx.x * 256 + threadIdx.x;
    int b = i >> 17;
    int n = i & (NPTS - 1);
    const float* p = pts + (size_t)i * 3;
    unsigned q[3];
#pragma unroll
    for (int a = 0; a < 3; a++) {
        float mn = fdec(g_mm[b * 6 + a * 2]);
        float mx = fdec(g_mm[b * 6 + a * 2 + 1]);
        float sc = fmaxf(__fsub_rn(mx, mn), 1e-8f);
        float r  = __frcp_rn(sc);
        float nr = __fmul_rn(__fsub_rn(p[a], mn), r);
        float tq = __fmul_rn(nr, 1023.0f);
        int qi = (int)tq;
        qi = max(0, min(qi, 1023));
        q[a] = (unsigned)qi;
    }
    unsigned mort = (expand10(q[0]) << 2) | (expand10(q[1]) << 1) | expand10(q[2]);
    unsigned* kin = (unsigned*)g_keys;
    unsigned* vin = kin + BN;
    kin[i] = ((unsigned)(b & 3) << 30) | mort;
    vin[i] = (unsigned)n;
}

// ---------------- K4: sort_idx + gather (range version) ----------------
__global__ void __launch_bounds__(256) k_gather(const float* __restrict__ pts,
                                                float* __restrict__ out, int write_idx,
                                                int i0) {
    int i = i0 + blockIdx.x * 256 + threadIdx.x;
    int b = i >> 17;
    const unsigned* vout = (const unsigned*)g_keys_out + BN;
    int idx = (int)vout[i];
    if (write_idx) out[TOK + CEN + i] = (float)idx;
    const float* s = pts + (((size_t)b << 17) + (size_t)idx) * 3;
    float* d = g_sp + (size_t)i * 3;
    d[0] = s[0]; d[1] = s[1]; d[2] = s[2];
}

// ---------------- K5: centroids + fused pos-MLP layer 1 (range version) ----------------
__global__ void __launch_bounds__(128) k_cent(const float* __restrict__ Wp1,
                                              const float* __restrict__ bp1,
                                              float* __restrict__ out, int write_cent,
                                              int m0, int mend) {
    __shared__ float Wp1s[192], bp1s[64];
    int t = threadIdx.x;
    if (t < 64) {
        Wp1s[t] = Wp1[t]; Wp1s[64 + t] = Wp1[64 + t]; Wp1s[128 + t] = Wp1[128 + t];
        bp1s[t] = bp1[t];
    }
    __syncthreads();
    int m = m0 + blockIdx.x * 128 + t;
    if (m >= mend) return;
    int b = m / LWIN, l = m - b * LWIN;
    const float* sp = g_sp + ((size_t)b * NPTS + (size_t)l * STRIDEW) * 3;
    float sx = 0.f, sy = 0.f, sz = 0.f;
#pragma unroll
    for (int p = 0; p < PATCHW; p++) {
        sx += sp[p * 3 + 0]; sy += sp[p * 3 + 1]; sz += sp[p * 3 + 2];
    }
    float cx = sx / 32.0f, cy = sy / 32.0f, cz = sz / 32.0f;
    g_cent[m * 3 + 0] = cx; g_cent[m * 3 + 1] = cy; g_cent[m * 3 + 2] = cz;
    if (write_cent) {
        out[TOK + m * 3 + 0] = cx; out[TOK + m * 3 + 1] = cy; out[TOK + m * 3 + 2] = cz;
    }
    size_t o = (size_t)m * COMBK + 128;
#pragma unroll 8
    for (int ch = 0; ch < 64; ch++) {
        float v = fmaf(cz, Wp1s[128 + ch], fmaf(cy, Wp1s[64 + ch], fmaf(cx, Wp1s[ch], bp1s[ch])));
        v = fmaxf(v, 0.f);
        __nv_bfloat16 hi, mid;
        bf16split(v, hi, mid);
        g_comb_hi[o + ch] = hi; g_comb_mid[o + ch] = mid;
    }
}

// ---------------- K_geo: mma.sync bf16-split GEMM + maxpool (R9 frozen version) ----------------
#define GW    16        // windows per block
#define HSTR  72        // bf16 per h row (144B = 9x16B)
#define WSTR  136       // bf16 per W2 row (272B = 17x16B)

__global__ void __launch_bounds__(128) k_geo(const float* __restrict__ W1,
                                             const float* __restrict__ b1,
                                             const float* __restrict__ W2,
                                             const float* __restrict__ b2) {
    __shared__ __align__(16) __nv_bfloat16 w2hi_s[64 * WSTR];
    __shared__ __align__(16) __nv_bfloat16 w2mid_s[64 * WSTR];
    __shared__ __align__(16) __nv_bfloat16 hhi_s[32 * HSTR];
    __shared__ __align__(16) __nv_bfloat16 hmid_s[32 * HSTR];
    __shared__ float W1s[192], b1s[64], b2s[128];

    int t = threadIdx.x, wi = t >> 5, lane = t & 31;

    if (t < 64) {
        W1s[t] = W1[t]; W1s[64 + t] = W1[64 + t]; W1s[128 + t] = W1[128 + t];
        b1s[t] = b1[t];
    }
    b2s[t] = b2[t];
    for (int i = t; i < 8192; i += 128) {
        int k = i >> 7, c = i & 127;
        float v = W2[i];
        __nv_bfloat16 hi, mid;
        bf16split(v, hi, mid);
        w2hi_s[k * WSTR + c]  = hi;
        w2mid_s[k * WSTR + c] = mid;
    }
    __syncthreads();

    uint32_t hhi_b = smem_u32(hhi_s), hmid_b = smem_u32(hmid_s);
    uint32_t w2hi_b = smem_u32(w2hi_s), w2mid_b = smem_u32(w2mid_s);

    int p  = t & 31;
    int kb = (t >> 5) * 16;

    uint32_t aoff = (uint32_t)(lane & 15) * (HSTR * 2) + (uint32_t)((lane >> 4) & 1) * 16;
    uint32_t boff = (uint32_t)(lane & 15) * (WSTR * 2) + (uint32_t)(wi * 32) * 2;

    for (int w = 0; w < GW; w++) {
        int mi = blockIdx.x * GW + w;
        int m  = min(mi, BL - 1);
        int b  = m / LWIN, l = m - b * LWIN;

        {
            const float* sp = g_sp + ((size_t)b * NPTS + (size_t)l * STRIDEW + p) * 3;
            float lx = sp[0] - g_cent[m * 3 + 0];
            float ly = sp[1] - g_cent[m * 3 + 1];
            float lz = sp[2] - g_cent[m * 3 + 2];
#pragma unroll
            for (int j = 0; j < 16; j += 2) {
                int k = kb + j;
                float v0 = fmaxf(fmaf(lz, W1s[128 + k],
                           fmaf(ly, W1s[64 + k], fmaf(lx, W1s[k], b1s[k]))), 0.f);
                float v1 = fmaxf(fmaf(lz, W1s[128 + k + 1],
                           fmaf(ly, W1s[64 + k + 1], fmaf(lx, W1s[k + 1], b1s[k + 1]))), 0.f);
                uint32_t h2;
                asm("cvt.rn.bf16x2.f32 %0, %1, %2;" : "=r"(h2) : "f"(v1), "f"(v0));
                float h0f = __uint_as_float(h2 << 16);
                float h1f = __uint_as_float(h2 & 0xFFFF0000u);
                uint32_t m2;
                asm("cvt.rn.bf16x2.f32 %0, %1, %2;" : "=r"(m2) : "f"(v1 - h1f), "f"(v0 - h0f));
                *(uint32_t*)&hhi_s[p * HSTR + k]  = h2;
                *(uint32_t*)&hmid_s[p * HSTR + k] = m2;
            }
        }
        __syncthreads();

        float acc[2][4][4] = {};
#pragma unroll
        for (int kt = 0; kt < 4; kt++) {
            uint32_t aH[2][4], aM[2][4];
            uint32_t ak = (uint32_t)(kt * 32);
            ldsm4(aH[0], hhi_b  + aoff + ak);
            ldsm4(aH[1], hhi_b  + aoff + ak + 16 * (HSTR * 2));
            ldsm4(aM[0], hmid_b + aoff + ak);
            ldsm4(aM[1], hmid_b + aoff + ak + 16 * (HSTR * 2));
            uint32_t bk = (uint32_t)(kt * 16) * (WSTR * 2);
#pragma unroll
            for (int nt = 0; nt < 4; nt++) {
                uint32_t bH[2], bM[2];
                uint32_t bn = (uint32_t)(nt * 16);
                ldsm2t(bH, w2hi_b  + boff + bk + bn);
                ldsm2t(bM, w2mid_b + boff + bk + bn);
#pragma unroll
                for (int mt = 0; mt < 2; mt++) {
                    mma_bf16(acc[mt][nt], aH[mt], bH);
                    mma_bf16(acc[mt][nt], aH[mt], bM);
                    mma_bf16(acc[mt][nt], aM[mt], bH);
                }
            }
        }

        if (mi < BL) {
#pragma unroll
            for (int nt = 0; nt < 4; nt++) {
                float m0 = fmaxf(fmaxf(acc[0][nt][0], acc[0][nt][2]),
                                 fmaxf(acc[1][nt][0], acc[1][nt][2]));
                float m1 = fmaxf(fmaxf(acc[0][nt][1], acc[0][nt][3]),
                                 fmaxf(acc[1][nt][1], acc[1][nt][3]));
#pragma unroll
                for (int s = 4; s <= 16; s <<= 1) {
                    m0 = fmaxf(m0, __shfl_xor_sync(0xffffffffu, m0, s));
                    m1 = fmaxf(m1, __shfl_xor_sync(0xffffffffu, m1, s));
                }
                if (lane < 4) {
                    int c = wi * 32 + nt * 8 + 2 * lane;
                    float v0 = fmaxf(m0 + b2s[c], 0.f);
                    float v1 = fmaxf(m1 + b2s[c + 1], 0.f);
                    __nv_bfloat16 h0, d0, h1, d1;
                    bf16split(v0, h0, d0);
                    bf16split(v1, h1, d1);
                    size_t o = (size_t)mi * COMBK + c;
                    g_comb_hi[o] = h0;  g_comb_hi[o + 1] = h1;
                    g_comb_mid[o] = d0; g_comb_mid[o + 1] = d1;
                }
            }
        }
        __syncthreads();
    }
}

// ---------------- K7: tokens = comb(BLx192) @ wb(192x256) + bfold ----------------
#define ASTR 200
#define BSTR 72
#define PA_HI  0
#define PA_MID (PA_HI + 64 * ASTR * 2)
#define PB_HI  (PA_MID + 64 * ASTR * 2)
#define PB_MID (PB_HI + 192 * BSTR * 2)
#define P_TOTAL (PB_MID + 192 * BSTR * 2)

__global__ void __launch_bounds__(256) k_proj(float* __restrict__ out) {
    extern __shared__ __align__(16) unsigned char ps[];
    int t = threadIdx.x, wid = t >> 5, lane = t & 31;
    int row0 = blockIdx.x * 64;

#pragma unroll
    for (int j = 0; j < 6; j++) {
        int idx = t + 256 * j;
        int r = idx / 24, kq = (idx % 24) * 8;
        size_t src = (size_t)(row0 + r) * COMBK + kq;
        *(uint4*)(ps + PA_HI  + (r * ASTR + kq) * 2) = *(const uint4*)(g_comb_hi + src);
        *(uint4*)(ps + PA_MID + (r * ASTR + kq) * 2) = *(const uint4*)(g_comb_mid + src);
    }

    int wm = wid & 1, wn = wid >> 1;
    uint32_t aHb = smem_u32(ps + PA_HI), aMb = smem_u32(ps + PA_MID);
    uint32_t bHb = smem_u32(ps + PB_HI), bMb = smem_u32(ps + PB_MID);
    uint32_t aoff = (uint32_t)(lane & 15) * (ASTR * 2) + (uint32_t)((lane >> 4) & 1) * 16;
    uint32_t boff = (uint32_t)(lane & 15) * (BSTR * 2) + (uint32_t)(wn * 16) * 2;

    for (int c4 = 0; c4 < 4; c4++) {
        int col0 = c4 * 64;
        __syncthreads();
#pragma unroll
        for (int j = 0; j < 6; j++) {
            int idx = t + 256 * j;
            int k = idx / 8, nq = (idx % 8) * 8;
            size_t src = (size_t)k * 256 + col0 + nq;
            *(uint4*)(ps + PB_HI  + (k * BSTR + nq) * 2) = *(const uint4*)(g_wb_hi + src);
            *(uint4*)(ps + PB_MID + (k * BSTR + nq) * 2) = *(const uint4*)(g_wb_mid + src);
        }
        __syncthreads();

        float acc[2][2][4] = {};
#pragma unroll
        for (int kt = 0; kt < 12; kt++) {
            uint32_t aH[2][4], aM[2][4];
#pragma unroll
            for (int mt = 0; mt < 2; mt++) {
                uint32_t ro = (uint32_t)((wm * 32 + mt * 16) * (ASTR * 2)) + kt * 32;
                ldsm4(aH[mt], aHb + aoff + ro);
                ldsm4(aM[mt], aMb + aoff + ro);
            }
            uint32_t bk = (uint32_t)(kt * 16) * (BSTR * 2);
#pragma unroll
            for (int nt = 0; nt < 2; nt++) {
                uint32_t bH[2], bM[2];
                ldsm2t(bH, bHb + boff + bk + nt * 16);
                ldsm2t(bM, bMb + boff + bk + nt * 16);
#pragma unroll
                for (int mt = 0; mt < 2; mt++) {
                    mma_bf16(acc[mt][nt], aH[mt], bH);
                    mma_bf16(acc[mt][nt], aH[mt], bM);
                    mma_bf16(acc[mt][nt], aM[mt], bH);
                }
            }
        }

#pragma unroll
        for (int mt = 0; mt < 2; mt++)
#pragma unroll
            for (int nt = 0; nt < 2; nt++) {
                int r = row0 + wm * 32 + mt * 16 + (lane >> 2);
                int c = col0 + wn * 16 + nt * 8 + (lane & 3) * 2;
                float b0 = g_bfold[c], b1 = g_bfold[c + 1];
                if (r < BL) {
                    out[(size_t)r * 256 + c]     = acc[mt][nt][0] + b0;
                    out[(size_t)r * 256 + c + 1] = acc[mt][nt][1] + b1;
                }
                if (r + 8 < BL) {
                    out[(size_t)(r + 8) * 256 + c]     = acc[mt][nt][2] + b0;
                    out[(size_t)(r + 8) * 256 + c + 1] = acc[mt][nt][3] + b1;
                }
            }
    }
}

// ---------------- launch ----------------
extern "C" void kernel_launch(void* const* d_in, const int* in_sizes, int n_in,
                              void* d_out, int out_size) {
    const float* points = (const float*)d_in[0];
    const float* W1   = (const float*)d_in[1];
    const float* b1   = (const float*)d_in[2];
    const float* W2   = (const float*)d_in[3];
    const float* b2   = (const float*)d_in[4];
    const float* Wp1  = (const float*)d_in[5];
    const float* bp1  = (const float*)d_in[6];
    const float* Wp2  = (const float*)d_in[7];
    const float* bp2  = (const float*)d_in[8];
    const float* Wproj = (const float*)d_in[9];
    const float* bproj = (const float*)d_in[10];
    float* out = (float*)d_out;

    int write_cent = (out_size >= TOK + CEN) ? 1 : 0;
    int write_idx  = (out_size >= TOK + CEN + IDXN) ? 1 : 0;

    // one side stream + 3 events (same footprint as the passing R14 run)
    static cudaStream_t s2 = nullptr;
    static cudaEvent_t ev_begin = nullptr, ev_fork = nullptr, ev_join = nullptr;
    if (s2 == nullptr) {
        cudaStreamCreateWithFlags(&s2, cudaStreamNonBlocking);
        cudaEventCreateWithFlags(&ev_begin, cudaEventDisableTiming);
        cudaEventCreateWithFlags(&ev_fork, cudaEventDisableTiming);
        cudaEventCreateWithFlags(&ev_join, cudaEventDisableTiming);
    }

    cudaFuncSetAttribute(k_proj, cudaFuncAttributeMaxDynamicSharedMemorySize, P_TOTAL);

    // fold on the side stream, overlapping minmax/keys/sort-half-0
    cudaEventRecord(ev_begin, 0);
    cudaStreamWaitEvent(s2, ev_begin, 0);
    k_fold<<<193, 256, 0, s2>>>(Wproj, Wp2, bp2, bproj);

    k_reset<<<1, 64>>>();
    k_minmax<<<BATCH * 64, 256>>>(points);
    k_keys<<<BN / 256, 256>>>(points);

    void* d_temp = nullptr;
    unsigned long long* sym_in = nullptr;
    unsigned long long* sym_out = nullptr;
    cudaGetSymbolAddress(&d_temp, g_temp);
    cudaGetSymbolAddress((void**)&sym_in, g_keys);
    cudaGetSymbolAddress((void**)&sym_out, g_keys_out);
    unsigned* kin  = (unsigned*)sym_in;
    unsigned* vin  = kin + BN;
    unsigned* kout = (unsigned*)sym_out;
    unsigned* vout = kout + BN;
    unsigned char* temp0 = (unsigned char*)d_temp;
    unsigned char* temp1 = temp0 + (64u * 1024u * 1024u);

    // Two pipelines, one per half (4 batches each):
    //   main: sort0 -> gather0 -> cent0
    //   s2:   fold -> sort1 -> gather1 -> cent1
    // Halves touch disjoint regions of g_sp/g_cent/g_comb/out (split at batch 4).
    size_t temp_bytes = 0;
    cub::DeviceRadixSort::SortPairs(nullptr, temp_bytes, kin, kout, vin, vout,
                                    BN / 2, 0, 32);
    if (temp_bytes <= 64u * 1024u * 1024u) {
        cudaEventRecord(ev_fork, 0);
        cudaStreamWaitEvent(s2, ev_fork, 0);     // s2: after fold, wait for keys
        size_t tb0 = temp_bytes, tb1 = temp_bytes;
        cub::DeviceRadixSort::SortPairs((void*)temp0, tb0, kin, kout, vin, vout,
                                        BN / 2, 0, 32, (cudaStream_t)0);
        cub::DeviceRadixSort::SortPairs((void*)temp1, tb1, kin + BN / 2, kout + BN / 2,
                                        vin + BN / 2, vout + BN / 2, BN / 2, 0, 32, s2);

        // half 0 on main stream
        k_gather<<<(BN / 2) / 256, 256>>>(points, out, write_idx, 0);
        k_cent<<<(HALFW + 127) / 128, 128>>>(Wp1, bp1, out, write_cent, 0, HALFW);
        // half 1 on s2
        k_gather<<<(BN / 2) / 256, 256, 0, s2>>>(points, out, write_idx, BN / 2);
        k_cent<<<(BL - HALFW + 127) / 128, 128, 0, s2>>>(Wp1, bp1, out, write_cent,
                                                         HALFW, BL);
        cudaEventRecord(ev_join, s2);            // orders fold, sort1, gather1, cent1
        cudaStreamWaitEvent((cudaStream_t)0, ev_join, 0);
    }

    k_geo<<<(BL + GW - 1) / GW, 128>>>(W1, b1, W2, b2);
    k_proj<<<BLP / 64, 256, P_TOTAL>>>(out);
}

// round 16
// speedup vs baseline: 1.1305x; 1.0073x over previous
#include <cuda_runtime.h>
#include <cuda_bf16.h>
#include <cub/cub.cuh>
#include <cstdint>

// ---------------- problem constants ----------------
#define BATCH   8
#define NPTS    131072
#define PATCHW  32
#define STRIDEW 16
#define LWIN    8191                    // (131072-32)/16 + 1
#define BL      (BATCH*LWIN)            // 65528
#define BLP     65536                   // padded rows for tile overrun
#define BN      (BATCH*NPTS)            // 1048576
#define TOK     (BL*256)                // tokens elems
#define CEN     (BL*3)                  // centroid elems
#define IDXN    BN                      // sort_idx elems
#define COMBK   192                     // [geo(128) | hp(64)]
#define HALFW   (4*LWIN)                // windows in half (32764)

// ---------------- static device scratch ----------------
__device__ __align__(256) unsigned long long g_keys[BN];      // holds 2x uint32[BN]: keys | vals
__device__ __align__(256) unsigned long long g_keys_out[BN];  // holds 2x uint32[BN]
__device__ __align__(256) unsigned char      g_temp[128u * 1024u * 1024u];
__device__ unsigned                          g_mm[48];
__device__ __align__(16) float               g_sp[BN * 3];
__device__ float                             g_cent[BL * 3];
__device__ __align__(16) __nv_bfloat16       g_comb_hi[(size_t)BLP * COMBK];   // zero-init
__device__ __align__(16) __nv_bfloat16       g_comb_mid[(size_t)BLP * COMBK];  // zero-init
__device__ __align__(16) __nv_bfloat16       g_wb_hi[192 * 256];
__device__ __align__(16) __nv_bfloat16       g_wb_mid[192 * 256];
__device__ __align__(16) float               g_bfold[256];

// ---------------- mma.sync helpers (sm_80+ PTX) ----------------
__device__ __forceinline__ uint32_t smem_u32(const void* p) {
    uint32_t a;
    asm("{ .reg .u64 t; cvta.to.shared.u64 t, %1; cvt.u32.u64 %0, t; }" : "=r"(a) : "l"(p));
    return a;
}
__device__ __forceinline__ void ldsm4(uint32_t* r, uint32_t addr) {
    asm volatile("ldmatrix.sync.aligned.m8n8.x4.shared.b16 {%0,%1,%2,%3}, [%4];"
        : "=r"(r[0]), "=r"(r[1]), "=r"(r[2]), "=r"(r[3]) : "r"(addr));
}
__device__ __forceinline__ void ldsm2t(uint32_t* r, uint32_t addr) {
    asm volatile("ldmatrix.sync.aligned.m8n8.x2.trans.shared.b16 {%0,%1}, [%2];"
        : "=r"(r[0]), "=r"(r[1]) : "r"(addr));
}
__device__ __forceinline__ void mma_bf16(float* d, const uint32_t* a, const uint32_t* b) {
    asm volatile("mma.sync.aligned.m16n8k16.row.col.f32.bf16.bf16.f32 "
        "{%0,%1,%2,%3}, {%4,%5,%6,%7}, {%8,%9}, {%0,%1,%2,%3};"
        : "+f"(d[0]), "+f"(d[1]), "+f"(d[2]), "+f"(d[3])
        : "r"(a[0]), "r"(a[1]), "r"(a[2]), "r"(a[3]), "r"(b[0]), "r"(b[1]));
}
__device__ __forceinline__ void bf16split(float v, __nv_bfloat16& hi, __nv_bfloat16& mid) {
    hi = __float2bfloat16_rn(v);
    mid = __float2bfloat16_rn(v - __bfloat162float(hi));
}

// ---------------- misc helpers ----------------
__device__ __forceinline__ unsigned fenc(float f) {
    unsigned u = __float_as_uint(f);
    return (u & 0x80000000u) ? ~u : (u | 0x80000000u);
}
__device__ __forceinline__ float fdec(unsigned u) {
    return (u & 0x80000000u) ? __uint_as_float(u ^ 0x80000000u) : __uint_as_float(~u);
}
__device__ __forceinline__ unsigned expand10(unsigned v) {
    v &= 0x3FFu;
    v = (v | (v << 16)) & 0x030000FFu;
    v = (v | (v << 8))  & 0x0300F00Fu;
    v = (v | (v << 4))  & 0x030C30C3u;
    v = (v | (v << 2))  & 0x09249249u;
    return v;
}

// ---------------- K: g_mm reset ----------------
__global__ void k_reset() {
    int t = threadIdx.x;
    if (t < 48) g_mm[t] = (t & 1) ? 0u : 0xFFFFFFFFu;
}

// ---------------- K: weight fold -> bf16 split (side stream) ----------------
__global__ void __launch_bounds__(256) k_fold(const float* __restrict__ Wproj,
                                              const float* __restrict__ Wp2,
                                              const float* __restrict__ bp2,
                                              const float* __restrict__ bproj) {
    int r = blockIdx.x, c = threadIdx.x;
    if (r < 128) {
        __nv_bfloat16 hi, mid;
        bf16split(Wproj[r * 256 + c], hi, mid);
        g_wb_hi[r * 256 + c] = hi; g_wb_mid[r * 256 + c] = mid;
    } else if (r < 192) {
        int d = r - 128;
        float s = 0.f;
        for (int j = 0; j < 128; j++)
            s = fmaf(Wp2[d * 128 + j], Wproj[(128 + j) * 256 + c], s);
        __nv_bfloat16 hi, mid;
        bf16split(s, hi, mid);
        g_wb_hi[r * 256 + c] = hi; g_wb_mid[r * 256 + c] = mid;
    } else {
        float s = bproj[c];
        for (int d = 0; d < 128; d++)
            s = fmaf(bp2[d], Wproj[(128 + d) * 256 + c], s);
        g_bfold[c] = s;
    }
}

// ---------------- K1/K2 ----------------
__global__ void __launch_bounds__(256) k_minmax(const float* __restrict__ pts) {
    int b = blockIdx.x >> 6, chunk = blockIdx.x & 63, t = threadIdx.x;
    unsigned mn0 = ~0u, mn1 = ~0u, mn2 = ~0u, mx0 = 0u, mx1 = 0u, mx2 = 0u;
    size_t base = (size_t)b * NPTS + (size_t)chunk * 2048;
    for (int j = t; j < 2048; j += 256) {
        const float* p = pts + (base + j) * 3;
        unsigned e0 = fenc(p[0]), e1 = fenc(p[1]), e2 = fenc(p[2]);
        mn0 = min(mn0, e0); mx0 = max(mx0, e0);
        mn1 = min(mn1, e1); mx1 = max(mx1, e1);
        mn2 = min(mn2, e2); mx2 = max(mx2, e2);
    }
    mn0 = __reduce_min_sync(0xffffffffu, mn0); mx0 = __reduce_max_sync(0xffffffffu, mx0);
    mn1 = __reduce_min_sync(0xffffffffu, mn1); mx1 = __reduce_max_sync(0xffffffffu, mx1);
    mn2 = __reduce_min_sync(0xffffffffu, mn2); mx2 = __reduce_max_sync(0xffffffffu, mx2);
    __shared__ unsigned s[6];
    if (t < 6) s[t] = (t < 3) ? 0xFFFFFFFFu : 0u;
    __syncthreads();
    if ((t & 31) == 0) {
        atomicMin(&s[0], mn0); atomicMin(&s[1], mn1); atomicMin(&s[2], mn2);
        atomicMax(&s[3], mx0); atomicMax(&s[4], mx1); atomicMax(&s[5], mx2);
    }
    __syncthreads();
    if (t < 3)      atomicMin(&g_mm[b * 6 + t * 2], s[t]);
    else if (t < 6) atomicMax(&g_mm[b * 6 + (t - 3) * 2 + 1], s[t]);
}

// 32-bit keys: (b&3)<<30 | morton.  Values: n.  Sorted in two halves (4 batches each).
__global__ void __launch_bounds__(256) k_keys(const float* __restrict__ pts) {
    int i = blockIdx.x * 256 + threadIdx.x;
    int b = i >> 17;
    int n = i & (NPTS - 1);
    const float* p = pts + (size_t)i * 3;
    unsigned q[3];
#pragma unroll
    for (int a = 0; a < 3; a++) {
        float mn = fdec(g_mm[b * 6 + a * 2]);
        float mx = fdec(g_mm[b * 6 + a * 2 + 1]);
        float sc = fmaxf(__fsub_rn(mx, mn), 1e-8f);
        float r  = __frcp_rn(sc);
        float nr = __fmul_rn(__fsub_rn(p[a], mn), r);
        float tq = __fmul_rn(nr, 1023.0f);
        int qi = (int)tq;
        qi = max(0, min(qi, 1023));
        q[a] = (unsigned)qi;
    }
    unsigned mort = (expand10(q[0]) << 2) | (expand10(q[1]) << 1) | expand10(q[2]);
    unsigned* kin = (unsigned*)g_keys;
    unsigned* vin = kin + BN;
    kin[i] = ((unsigned)(b & 3) << 30) | mort;
    vin[i] = (unsigned)n;
}

// ---------------- K4: sort_idx + gather (range version) ----------------
__global__ void __launch_bounds__(256) k_gather(const float* __restrict__ pts,
                                                float* __restrict__ out, int write_idx,
                                                int i0) {
    int i = i0 + blockIdx.x * 256 + threadIdx.x;
    int b = i >> 17;
    const unsigned* vout = (const unsigned*)g_keys_out + BN;
    int idx = (int)vout[i];
    if (write_idx) out[TOK + CEN + i] = (float)idx;
    const float* s = pts + (((size_t)b << 17) + (size_t)idx) * 3;
    float* d = g_sp + (size_t)i * 3;
    d[0] = s[0]; d[1] = s[1]; d[2] = s[2];
}

// ---------------- K5: centroids + fused pos-MLP layer 1 (range version) ----------------
__global__ void __launch_bounds__(128) k_cent(const float* __restrict__ Wp1,
                                              const float* __restrict__ bp1,
                                              float* __restrict__ out, int write_cent,
                                              int m0, int mend) {
    __shared__ float Wp1s[192], bp1s[64];
    int t = threadIdx.x;
    if (t < 64) {
        Wp1s[t] = Wp1[t]; Wp1s[64 + t] = Wp1[64 + t]; Wp1s[128 + t] = Wp1[128 + t];
        bp1s[t] = bp1[t];
    }
    __syncthreads();
    int m = m0 + blockIdx.x * 128 + t;
    if (m >= mend) return;
    int b = m / LWIN, l = m - b * LWIN;
    const float* sp = g_sp + ((size_t)b * NPTS + (size_t)l * STRIDEW) * 3;
    float sx = 0.f, sy = 0.f, sz = 0.f;
#pragma unroll
    for (int p = 0; p < PATCHW; p++) {
        sx += sp[p * 3 + 0]; sy += sp[p * 3 + 1]; sz += sp[p * 3 + 2];
    }
    float cx = sx / 32.0f, cy = sy / 32.0f, cz = sz / 32.0f;
    g_cent[m * 3 + 0] = cx; g_cent[m * 3 + 1] = cy; g_cent[m * 3 + 2] = cz;
    if (write_cent) {
        out[TOK + m * 3 + 0] = cx; out[TOK + m * 3 + 1] = cy; out[TOK + m * 3 + 2] = cz;
    }
    size_t o = (size_t)m * COMBK + 128;
#pragma unroll 8
    for (int ch = 0; ch < 64; ch++) {
        float v = fmaf(cz, Wp1s[128 + ch], fmaf(cy, Wp1s[64 + ch], fmaf(cx, Wp1s[ch], bp1s[ch])));
        v = fmaxf(v, 0.f);
        __nv_bfloat16 hi, mid;
        bf16split(v, hi, mid);
        g_comb_hi[o + ch] = hi; g_comb_mid[o + ch] = mid;
    }
}

// ---------------- K_geo: mma.sync bf16-split GEMM + maxpool (range version of R9 core) ----------------
#define GW    16        // windows per block
#define HSTR  72        // bf16 per h row (144B = 9x16B)
#define WSTR  136       // bf16 per W2 row (272B = 17x16B)

__global__ void __launch_bounds__(128) k_geo(const float* __restrict__ W1,
                                             const float* __restrict__ b1,
                                             const float* __restrict__ W2,
                                             const float* __restrict__ b2,
                                             int m0, int mend) {
    __shared__ __align__(16) __nv_bfloat16 w2hi_s[64 * WSTR];
    __shared__ __align__(16) __nv_bfloat16 w2mid_s[64 * WSTR];
    __shared__ __align__(16) __nv_bfloat16 hhi_s[32 * HSTR];
    __shared__ __align__(16) __nv_bfloat16 hmid_s[32 * HSTR];
    __shared__ float W1s[192], b1s[64], b2s[128];

    int t = threadIdx.x, wi = t >> 5, lane = t & 31;

    if (t < 64) {
        W1s[t] = W1[t]; W1s[64 + t] = W1[64 + t]; W1s[128 + t] = W1[128 + t];
        b1s[t] = b1[t];
    }
    b2s[t] = b2[t];
    for (int i = t; i < 8192; i += 128) {
        int k = i >> 7, c = i & 127;
        float v = W2[i];
        __nv_bfloat16 hi, mid;
        bf16split(v, hi, mid);
        w2hi_s[k * WSTR + c]  = hi;
        w2mid_s[k * WSTR + c] = mid;
    }
    __syncthreads();

    uint32_t hhi_b = smem_u32(hhi_s), hmid_b = smem_u32(hmid_s);
    uint32_t w2hi_b = smem_u32(w2hi_s), w2mid_b = smem_u32(w2mid_s);

    int p  = t & 31;
    int kb = (t >> 5) * 16;

    uint32_t aoff = (uint32_t)(lane & 15) * (HSTR * 2) + (uint32_t)((lane >> 4) & 1) * 16;
    uint32_t boff = (uint32_t)(lane & 15) * (WSTR * 2) + (uint32_t)(wi * 32) * 2;

    for (int w = 0; w < GW; w++) {
        int mi = m0 + blockIdx.x * GW + w;
        int m  = min(mi, mend - 1);
        int b  = m / LWIN, l = m - b * LWIN;

        {
            const float* sp = g_sp + ((size_t)b * NPTS + (size_t)l * STRIDEW + p) * 3;
            float lx = sp[0] - g_cent[m * 3 + 0];
            float ly = sp[1] - g_cent[m * 3 + 1];
            float lz = sp[2] - g_cent[m * 3 + 2];
#pragma unroll
            for (int j = 0; j < 16; j += 2) {
                int k = kb + j;
                float v0 = fmaxf(fmaf(lz, W1s[128 + k],
                           fmaf(ly, W1s[64 + k], fmaf(lx, W1s[k], b1s[k]))), 0.f);
                float v1 = fmaxf(fmaf(lz, W1s[128 + k + 1],
                           fmaf(ly, W1s[64 + k + 1], fmaf(lx, W1s[k + 1], b1s[k + 1]))), 0.f);
                uint32_t h2;
                asm("cvt.rn.bf16x2.f32 %0, %1, %2;" : "=r"(h2) : "f"(v1), "f"(v0));
                float h0f = __uint_as_float(h2 << 16);
                float h1f = __uint_as_float(h2 & 0xFFFF0000u);
                uint32_t m2;
                asm("cvt.rn.bf16x2.f32 %0, %1, %2;" : "=r"(m2) : "f"(v1 - h1f), "f"(v0 - h0f));
                *(uint32_t*)&hhi_s[p * HSTR + k]  = h2;
                *(uint32_t*)&hmid_s[p * HSTR + k] = m2;
            }
        }
        __syncthreads();

        float acc[2][4][4] = {};
#pragma unroll
        for (int kt = 0; kt < 4; kt++) {
            uint32_t aH[2][4], aM[2][4];
            uint32_t ak = (uint32_t)(kt * 32);
            ldsm4(aH[0], hhi_b  + aoff + ak);
            ldsm4(aH[1], hhi_b  + aoff + ak + 16 * (HSTR * 2));
            ldsm4(aM[0], hmid_b + aoff + ak);
            ldsm4(aM[1], hmid_b + aoff + ak + 16 * (HSTR * 2));
            uint32_t bk = (uint32_t)(kt * 16) * (WSTR * 2);
#pragma unroll
            for (int nt = 0; nt < 4; nt++) {
                uint32_t bH[2], bM[2];
                uint32_t bn = (uint32_t)(nt * 16);
                ldsm2t(bH, w2hi_b  + boff + bk + bn);
                ldsm2t(bM, w2mid_b + boff + bk + bn);
#pragma unroll
                for (int mt = 0; mt < 2; mt++) {
                    mma_bf16(acc[mt][nt], aH[mt], bH);
                    mma_bf16(acc[mt][nt], aH[mt], bM);
                    mma_bf16(acc[mt][nt], aM[mt], bH);
                }
            }
        }

        if (mi < mend) {
#pragma unroll
            for (int nt = 0; nt < 4; nt++) {
                float m0v = fmaxf(fmaxf(acc[0][nt][0], acc[0][nt][2]),
                                  fmaxf(acc[1][nt][0], acc[1][nt][2]));
                float m1v = fmaxf(fmaxf(acc[0][nt][1], acc[0][nt][3]),
                                  fmaxf(acc[1][nt][1], acc[1][nt][3]));
#pragma unroll
                for (int s = 4; s <= 16; s <<= 1) {
                    m0v = fmaxf(m0v, __shfl_xor_sync(0xffffffffu, m0v, s));
                    m1v = fmaxf(m1v, __shfl_xor_sync(0xffffffffu, m1v, s));
                }
                if (lane < 4) {
                    int c = wi * 32 + nt * 8 + 2 * lane;
                    float v0 = fmaxf(m0v + b2s[c], 0.f);
                    float v1 = fmaxf(m1v + b2s[c + 1], 0.f);
                    __nv_bfloat16 h0, d0, h1, d1;
                    bf16split(v0, h0, d0);
                    bf16split(v1, h1, d1);
                    size_t o = (size_t)mi * COMBK + c;
                    g_comb_hi[o] = h0;  g_comb_hi[o + 1] = h1;
                    g_comb_mid[o] = d0; g_comb_mid[o + 1] = d1;
                }
            }
        }
        __syncthreads();
    }
}

// ---------------- K7: tokens = comb(BLx192) @ wb(192x256) + bfold ----------------
#define ASTR 200
#define BSTR 72
#define PA_HI  0
#define PA_MID (PA_HI + 64 * ASTR * 2)
#define PB_HI  (PA_MID + 64 * ASTR * 2)
#define PB_MID (PB_HI + 192 * BSTR * 2)
#define P_TOTAL (PB_MID + 192 * BSTR * 2)

__global__ void __launch_bounds__(256) k_proj(float* __restrict__ out) {
    extern __shared__ __align__(16) unsigned char ps[];
    int t = threadIdx.x, wid = t >> 5, lane = t & 31;
    int row0 = blockIdx.x * 64;

#pragma unroll
    for (int j = 0; j < 6; j++) {
        int idx = t + 256 * j;
        int r = idx / 24, kq = (idx % 24) * 8;
        size_t src = (size_t)(row0 + r) * COMBK + kq;
        *(uint4*)(ps + PA_HI  + (r * ASTR + kq) * 2) = *(const uint4*)(g_comb_hi + src);
        *(uint4*)(ps + PA_MID + (r * ASTR + kq) * 2) = *(const uint4*)(g_comb_mid + src);
    }

    int wm = wid & 1, wn = wid >> 1;
    uint32_t aHb = smem_u32(ps + PA_HI), aMb = smem_u32(ps + PA_MID);
    uint32_t bHb = smem_u32(ps + PB_HI), bMb = smem_u32(ps + PB_MID);
    uint32_t aoff = (uint32_t)(lane & 15) * (ASTR * 2) + (uint32_t)((lane >> 4) & 1) * 16;
    uint32_t boff = (uint32_t)(lane & 15) * (BSTR * 2) + (uint32_t)(wn * 16) * 2;

    for (int c4 = 0; c4 < 4; c4++) {
        int col0 = c4 * 64;
        __syncthreads();
#pragma unroll
        for (int j = 0; j < 6; j++) {
            int idx = t + 256 * j;
            int k = idx / 8, nq = (idx % 8) * 8;
            size_t src = (size_t)k * 256 + col0 + nq;
            *(uint4*)(ps + PB_HI  + (k * BSTR + nq) * 2) = *(const uint4*)(g_wb_hi + src);
            *(uint4*)(ps + PB_MID + (k * BSTR + nq) * 2) = *(const uint4*)(g_wb_mid + src);
        }
        __syncthreads();

        float acc[2][2][4] = {};
#pragma unroll
        for (int kt = 0; kt < 12; kt++) {
            uint32_t aH[2][4], aM[2][4];
#pragma unroll
            for (int mt = 0; mt < 2; mt++) {
                uint32_t ro = (uint32_t)((wm * 32 + mt * 16) * (ASTR * 2)) + kt * 32;
                ldsm4(aH[mt], aHb + aoff + ro);
                ldsm4(aM[mt], aMb + aoff + ro);
            }
            uint32_t bk = (uint32_t)(kt * 16) * (BSTR * 2);
#pragma unroll
            for (int nt = 0; nt < 2; nt++) {
                uint32_t bH[2], bM[2];
                ldsm2t(bH, bHb + boff + bk + nt * 16);
                ldsm2t(bM, bMb + boff + bk + nt * 16);
#pragma unroll
                for (int mt = 0; mt < 2; mt++) {
                    mma_bf16(acc[mt][nt], aH[mt], bH);
                    mma_bf16(acc[mt][nt], aH[mt], bM);
                    mma_bf16(acc[mt][nt], aM[mt], bH);
                }
            }
        }

#pragma unroll
        for (int mt = 0; mt < 2; mt++)
#pragma unroll
            for (int nt = 0; nt < 2; nt++) {
                int r = row0 + wm * 32 + mt * 16 + (lane >> 2);
                int c = col0 + wn * 16 + nt * 8 + (lane & 3) * 2;
                float b0 = g_bfold[c], b1 = g_bfold[c + 1];
                if (r < BL) {
                    out[(size_t)r * 256 + c]     = acc[mt][nt][0] + b0;
                    out[(size_t)r * 256 + c + 1] = acc[mt][nt][1] + b1;
                }
                if (r + 8 < BL) {
                    out[(size_t)(r + 8) * 256 + c]     = acc[mt][nt][2] + b0;
                    out[(size_t)(r + 8) * 256 + c + 1] = acc[mt][nt][3] + b1;
                }
            }
    }
}

// ---------------- launch ----------------
extern "C" void kernel_launch(void* const* d_in, const int* in_sizes, int n_in,
                              void* d_out, int out_size) {
    const float* points = (const float*)d_in[0];
    const float* W1   = (const float*)d_in[1];
    const float* b1   = (const float*)d_in[2];
    const float* W2   = (const float*)d_in[3];
    const float* b2   = (const float*)d_in[4];
    const float* Wp1  = (const float*)d_in[5];
    const float* bp1  = (const float*)d_in[6];
    const float* Wp2  = (const float*)d_in[7];
    const float* bp2  = (const float*)d_in[8];
    const float* Wproj = (const float*)d_in[9];
    const float* bproj = (const float*)d_in[10];
    float* out = (float*)d_out;

    int write_cent = (out_size >= TOK + CEN) ? 1 : 0;
    int write_idx  = (out_size >= TOK + CEN + IDXN) ? 1 : 0;

    // one side stream + 3 events (same footprint as the passing R14/R15 runs)
    static cudaStream_t s2 = nullptr;
    static cudaEvent_t ev_begin = nullptr, ev_fork = nullptr, ev_join = nullptr;
    if (s2 == nullptr) {
        cudaStreamCreateWithFlags(&s2, cudaStreamNonBlocking);
        cudaEventCreateWithFlags(&ev_begin, cudaEventDisableTiming);
        cudaEventCreateWithFlags(&ev_fork, cudaEventDisableTiming);
        cudaEventCreateWithFlags(&ev_join, cudaEventDisableTiming);
    }

    cudaFuncSetAttribute(k_proj, cudaFuncAttributeMaxDynamicSharedMemorySize, P_TOTAL);

    // fold on the side stream, overlapping minmax/keys/sort-half-0
    cudaEventRecord(ev_begin, 0);
    cudaStreamWaitEvent(s2, ev_begin, 0);
    k_fold<<<193, 256, 0, s2>>>(Wproj, Wp2, bp2, bproj);

    k_reset<<<1, 64>>>();
    k_minmax<<<BATCH * 64, 256>>>(points);
    k_keys<<<BN / 256, 256>>>(points);

    void* d_temp = nullptr;
    unsigned long long* sym_in = nullptr;
    unsigned long long* sym_out = nullptr;
    cudaGetSymbolAddress(&d_temp, g_temp);
    cudaGetSymbolAddress((void**)&sym_in, g_keys);
    cudaGetSymbolAddress((void**)&sym_out, g_keys_out);
    unsigned* kin  = (unsigned*)sym_in;
    unsigned* vin  = kin + BN;
    unsigned* kout = (unsigned*)sym_out;
    unsigned* vout = kout + BN;
    unsigned char* temp0 = (unsigned char*)d_temp;
    unsigned char* temp1 = temp0 + (64u * 1024u * 1024u);

    // Two pipelines, one per half (4 batches each):
    //   main: sort0 -> gather0 -> cent0 -> geo0
    //   s2:   fold -> sort1 -> gather1 -> cent1 -> geo1
    // Halves touch disjoint regions of g_sp/g_cent/g_comb/out (split at batch 4;
    // windows never straddle batches, HALFW = 4*LWIN).
    size_t temp_bytes = 0;
    cub::DeviceRadixSort::SortPairs(nullptr, temp_bytes, kin, kout, vin, vout,
                                    BN / 2, 0, 32);
    if (temp_bytes <= 64u * 1024u * 1024u) {
        cudaEventRecord(ev_fork, 0);
        cudaStreamWaitEvent(s2, ev_fork, 0);     // s2: after fold, wait for keys
        size_t tb0 = temp_bytes, tb1 = temp_bytes;
        cub::DeviceRadixSort::SortPairs((void*)temp0, tb0, kin, kout, vin, vout,
                                        BN / 2, 0, 32, (cudaStream_t)0);
        cub::DeviceRadixSort::SortPairs((void*)temp1, tb1, kin + BN / 2, kout + BN / 2,
                                        vin + BN / 2, vout + BN / 2, BN / 2, 0, 32, s2);

        // half 0 on main stream
        k_gather<<<(BN / 2) / 256, 256>>>(points, out, write_idx, 0);
        k_cent<<<(HALFW + 127) / 128, 128>>>(Wp1, bp1, out, write_cent, 0, HALFW);
        k_geo<<<(HALFW + GW - 1) / GW, 128>>>(W1, b1, W2, b2, 0, HALFW);
        // half 1 on s2
        k_gather<<<(BN / 2) / 256, 256, 0, s2>>>(points, out, write_idx, BN / 2);
        k_cent<<<(BL - HALFW + 127) / 128, 128, 0, s2>>>(Wp1, bp1, out, write_cent,
                                                         HALFW, BL);
        k_geo<<<(BL - HALFW + GW - 1) / GW, 128, 0, s2>>>(W1, b1, W2, b2, HALFW, BL);
        cudaEventRecord(ev_join, s2);            // orders fold, sort1, gather1, cent1, geo1
        cudaStreamWaitEvent((cudaStream_t)0, ev_join, 0);
    }

    k_proj<<<BLP / 64, 256, P_TOTAL>>>(out);
}